// round 2
// baseline (speedup 1.0000x reference)
#include <cuda_runtime.h>
#include <math.h>

// ---------------- problem constants ----------------
#define NNZ   240000
#define CIN   256
#define CCH   128
#define KGRP  12
#define NOUT  768            // plain packed: [ga 128 | la 128 | gb 128 | lb 128 | go 256]
#define RB    64             // rows per GEMM/epilogue block
#define NRB   (NNZ / RB)     // 3750

// ---------------- device scratch (static; no runtime alloc) ----------------
__device__ float g_Wt[CIN * NOUT];            // k-major packed weights [256][768]
__device__ float g_bcat[NOUT];                // packed bias
__device__ float g_Wlot[CCH * CIN];           // W_lo^T: [k=128][j=256]
__device__ float g_x[(size_t)NNZ * CIN];      // LN(values)           245.8 MB
__device__ float g_y[(size_t)NNZ * NOUT];     // raw GEMM out         737.3 MB
__device__ float g_a[(size_t)NNZ * CCH];      // a                    122.9 MB
__device__ float g_gate[(size_t)NNZ * CIN];   // sigmoid(go)          245.8 MB
__device__ float g_t[(size_t)NNZ * CCH];      // LN(tri)              122.9 MB
__device__ float g_Bpart[(size_t)NRB * KGRP * CCH];  // 23 MB
__device__ float g_B[KGRP * CCH];

__device__ __forceinline__ float sigf(float x) { return 1.0f / (1.0f + expf(-x)); }

// ---------------- kernel: pack weights (plain concatenation) ----------------
__global__ void k_pack(const float* __restrict__ Wga, const float* __restrict__ bga,
                       const float* __restrict__ Wla, const float* __restrict__ bla,
                       const float* __restrict__ Wgb, const float* __restrict__ bgb,
                       const float* __restrict__ Wlb, const float* __restrict__ blb,
                       const float* __restrict__ Wgo, const float* __restrict__ bgo,
                       const float* __restrict__ Wlo) {
    int idx = blockIdx.x * blockDim.x + threadIdx.x;
    if (idx < NOUT * CIN) {
        int p = idx / CIN;          // packed output col 0..767
        int k = idx % CIN;          // input dim 0..255
        const float* W; const float* bs; int c;
        if (p < 128)      { c = p;       W = Wga; bs = bga; }
        else if (p < 256) { c = p - 128; W = Wla; bs = bla; }
        else if (p < 384) { c = p - 256; W = Wgb; bs = bgb; }
        else if (p < 512) { c = p - 384; W = Wlb; bs = blb; }
        else              { c = p - 512; W = Wgo; bs = bgo; }
        g_Wt[k * NOUT + p] = W[c * CIN + k];
        if (k == 0) g_bcat[p] = bs[c];
    } else {
        int t = idx - NOUT * CIN;
        if (t < CCH * CIN) {
            int k = t / CIN;        // 0..127
            int j = t % CIN;        // 0..255
            g_Wlot[k * CIN + j] = Wlo[j * CCH + k];  // Wlo is [256,128]
        }
    }
}

// ---------------- kernel: input layernorm (1 warp / row) ----------------
__global__ void k_ln(const float* __restrict__ v,
                     const float* __restrict__ g, const float* __restrict__ b) {
    int row  = blockIdx.x * 8 + (threadIdx.x >> 5);
    int lane = threadIdx.x & 31;
    const float* vr = v + (size_t)row * CIN;
    float4 x0 = *(const float4*)(vr + lane * 4);
    float4 x1 = *(const float4*)(vr + 128 + lane * 4);
    float s = x0.x + x0.y + x0.z + x0.w + x1.x + x1.y + x1.z + x1.w;
    float q = x0.x*x0.x + x0.y*x0.y + x0.z*x0.z + x0.w*x0.w
            + x1.x*x1.x + x1.y*x1.y + x1.z*x1.z + x1.w*x1.w;
    #pragma unroll
    for (int o = 16; o; o >>= 1) {
        s += __shfl_xor_sync(0xffffffffu, s, o);
        q += __shfl_xor_sync(0xffffffffu, q, o);
    }
    float mu  = s * (1.0f / 256.0f);
    float var = fmaxf(q * (1.0f / 256.0f) - mu * mu, 0.0f);
    float rs  = rsqrtf(var + 1e-5f);
    float4 g0 = *(const float4*)(g + lane * 4);
    float4 g1 = *(const float4*)(g + 128 + lane * 4);
    float4 b0 = *(const float4*)(b + lane * 4);
    float4 b1 = *(const float4*)(b + 128 + lane * 4);
    float4 o0, o1;
    o0.x = (x0.x - mu) * rs * g0.x + b0.x;  o0.y = (x0.y - mu) * rs * g0.y + b0.y;
    o0.z = (x0.z - mu) * rs * g0.z + b0.z;  o0.w = (x0.w - mu) * rs * g0.w + b0.w;
    o1.x = (x1.x - mu) * rs * g1.x + b1.x;  o1.y = (x1.y - mu) * rs * g1.y + b1.y;
    o1.z = (x1.z - mu) * rs * g1.z + b1.z;  o1.w = (x1.w - mu) * rs * g1.w + b1.w;
    float* xr = g_x + (size_t)row * CIN;
    *(float4*)(xr + lane * 4)       = o0;
    *(float4*)(xr + 128 + lane * 4) = o1;
}

// ---------------- kernel: GEMM y = x @ Wt + bias  (M=240000, N=768, K=256) ----------------
// block tile 64x64, K-chunk 32, 256 threads, each thread 4x4.
__global__ void k_gemm768() {
    __shared__ float Xs[64][36];
    __shared__ float Ws[32][68];
    const int tid = threadIdx.x;
    const int tx  = tid & 15;   // col group
    const int ty  = tid >> 4;   // row group
    const size_t row0 = (size_t)blockIdx.x * 64;
    const int    col0 = blockIdx.y * 64;

    float acc[4][4];
    #pragma unroll
    for (int i = 0; i < 4; ++i)
        #pragma unroll
        for (int j = 0; j < 4; ++j) acc[i][j] = 0.0f;

    for (int kb = 0; kb < 256; kb += 32) {
        #pragma unroll
        for (int h = 0; h < 2; ++h) {
            int r  = (tid >> 3) + h * 32;       // 0..63
            int kq = (tid & 7) * 4;             // 0..28
            float4 xv = *(const float4*)(g_x + (row0 + r) * CIN + kb + kq);
            Xs[r][kq] = xv.x; Xs[r][kq+1] = xv.y; Xs[r][kq+2] = xv.z; Xs[r][kq+3] = xv.w;
        }
        #pragma unroll
        for (int h = 0; h < 2; ++h) {
            int kk = (tid >> 4) + h * 16;       // 0..31
            int cq = (tid & 15) * 4;            // 0..60
            float4 wv = *(const float4*)(g_Wt + (size_t)(kb + kk) * NOUT + col0 + cq);
            Ws[kk][cq] = wv.x; Ws[kk][cq+1] = wv.y; Ws[kk][cq+2] = wv.z; Ws[kk][cq+3] = wv.w;
        }
        __syncthreads();
        #pragma unroll 8
        for (int kk = 0; kk < 32; ++kk) {
            float xv[4], wv[4];
            #pragma unroll
            for (int i = 0; i < 4; ++i) xv[i] = Xs[ty * 4 + i][kk];
            #pragma unroll
            for (int j = 0; j < 4; ++j) wv[j] = Ws[kk][tx * 4 + j];
            #pragma unroll
            for (int i = 0; i < 4; ++i)
                #pragma unroll
                for (int j = 0; j < 4; ++j) acc[i][j] += xv[i] * wv[j];
        }
        __syncthreads();
    }
    #pragma unroll
    for (int i = 0; i < 4; ++i)
        #pragma unroll
        for (int j = 0; j < 4; ++j) {
            int c = col0 + tx * 4 + j;
            g_y[(row0 + ty * 4 + i) * NOUT + c] = acc[i][j] + g_bcat[c];
        }
}

// ---------------- kernel: epilogue 1 — a, gate, per-block B partials ----------------
__global__ void k_epi1() {
    __shared__ float Brows[64][129];
    const int tid = threadIdx.x;
    const size_t row0 = (size_t)blockIdx.x * 64;

    // a and b rows
    for (int t = tid; t < 64 * 128; t += 256) {
        int r  = t >> 7;
        int ch = t & 127;
        const float* yr = g_y + (row0 + r) * NOUT;
        g_a[(row0 + r) * CCH + ch] = sigf(yr[ch]) * yr[128 + ch];
        Brows[r][ch] = sigf(yr[256 + ch]) * yr[384 + ch];
    }
    // gate (separate array — idempotent across graph replays)
    for (int t = tid; t < 64 * 256; t += 256) {
        int r = t >> 8;
        int c = t & 255;
        g_gate[(row0 + r) * CIN + c] = sigf(g_y[(row0 + r) * NOUT + 512 + c]);
    }
    __syncthreads();
    // deterministic B partials: sum local rows whose global row % 12 == k
    int base = (int)(row0 % KGRP);
    for (int t = tid; t < KGRP * CCH; t += 256) {
        int k  = t >> 7;
        int ch = t & 127;
        int r0 = (k - base + KGRP) % KGRP;
        float s = 0.0f;
        for (int r = r0; r < 64; r += KGRP) s += Brows[r][ch];
        g_Bpart[(size_t)blockIdx.x * (KGRP * CCH) + t] = s;
    }
}

// ---------------- kernel: reduce B partials (deterministic) ----------------
__global__ void k_redB() {
    int d = blockIdx.x * 256 + threadIdx.x;   // 0..1535
    float s = 0.0f;
    for (int b = 0; b < NRB; ++b) s += g_Bpart[(size_t)b * (KGRP * CCH) + d];
    g_B[d] = s;
}

// ---------------- kernel: tri = a * B[row%12], layernorm over 128 ----------------
__global__ void k_tri_ln(const float* __restrict__ g, const float* __restrict__ b) {
    int row  = blockIdx.x * 8 + (threadIdx.x >> 5);
    int lane = threadIdx.x & 31;
    float4 av = *(const float4*)(g_a + (size_t)row * CCH + lane * 4);
    const float* Br = g_B + (row % KGRP) * CCH;
    float4 bv = *(const float4*)(Br + lane * 4);
    float t0 = av.x * bv.x, t1 = av.y * bv.y, t2 = av.z * bv.z, t3 = av.w * bv.w;
    float s = t0 + t1 + t2 + t3;
    float q = t0*t0 + t1*t1 + t2*t2 + t3*t3;
    #pragma unroll
    for (int o = 16; o; o >>= 1) {
        s += __shfl_xor_sync(0xffffffffu, s, o);
        q += __shfl_xor_sync(0xffffffffu, q, o);
    }
    float mu  = s * (1.0f / 128.0f);
    float var = fmaxf(q * (1.0f / 128.0f) - mu * mu, 0.0f);
    float rs  = rsqrtf(var + 1e-5f);
    float4 g4 = *(const float4*)(g + lane * 4);
    float4 b4 = *(const float4*)(b + lane * 4);
    float4 o4;
    o4.x = (t0 - mu) * rs * g4.x + b4.x;
    o4.y = (t1 - mu) * rs * g4.y + b4.y;
    o4.z = (t2 - mu) * rs * g4.z + b4.z;
    o4.w = (t3 - mu) * rs * g4.w + b4.w;
    *(float4*)(g_t + (size_t)row * CCH + lane * 4) = o4;
}

// ---------------- kernel: out = gate * (LN(tri) @ Wlo^T + b_lo) ----------------
// M=240000, N=256, K=128.  64x64 tile, K-chunk 32.
__global__ void k_gemm256(const float* __restrict__ blo, float* __restrict__ out) {
    __shared__ float Ts[64][36];
    __shared__ float Ws[32][68];
    const int tid = threadIdx.x;
    const int tx  = tid & 15;
    const int ty  = tid >> 4;
    const size_t row0 = (size_t)blockIdx.x * 64;
    const int    col0 = blockIdx.y * 64;

    float acc[4][4];
    #pragma unroll
    for (int i = 0; i < 4; ++i)
        #pragma unroll
        for (int j = 0; j < 4; ++j) acc[i][j] = 0.0f;

    for (int kb = 0; kb < 128; kb += 32) {
        #pragma unroll
        for (int h = 0; h < 2; ++h) {
            int r  = (tid >> 3) + h * 32;
            int kq = (tid & 7) * 4;
            float4 tv = *(const float4*)(g_t + (row0 + r) * CCH + kb + kq);
            Ts[r][kq] = tv.x; Ts[r][kq+1] = tv.y; Ts[r][kq+2] = tv.z; Ts[r][kq+3] = tv.w;
        }
        #pragma unroll
        for (int h = 0; h < 2; ++h) {
            int kk = (tid >> 4) + h * 16;
            int cq = (tid & 15) * 4;
            float4 wv = *(const float4*)(g_Wlot + (size_t)(kb + kk) * CIN + col0 + cq);
            Ws[kk][cq] = wv.x; Ws[kk][cq+1] = wv.y; Ws[kk][cq+2] = wv.z; Ws[kk][cq+3] = wv.w;
        }
        __syncthreads();
        #pragma unroll 8
        for (int kk = 0; kk < 32; ++kk) {
            float tv[4], wv[4];
            #pragma unroll
            for (int i = 0; i < 4; ++i) tv[i] = Ts[ty * 4 + i][kk];
            #pragma unroll
            for (int j = 0; j < 4; ++j) wv[j] = Ws[kk][tx * 4 + j];
            #pragma unroll
            for (int i = 0; i < 4; ++i)
                #pragma unroll
                for (int j = 0; j < 4; ++j) acc[i][j] += tv[i] * wv[j];
        }
        __syncthreads();
    }
    #pragma unroll
    for (int i = 0; i < 4; ++i) {
        size_t gr = row0 + ty * 4 + i;
        #pragma unroll
        for (int j = 0; j < 4; ++j) {
            int c = col0 + tx * 4 + j;
            float lin = acc[i][j] + blo[c];
            out[gr * CIN + c] = g_gate[gr * CIN + c] * lin;
        }
    }
}

// ---------------- launch ----------------
extern "C" void kernel_launch(void* const* d_in, const int* in_sizes, int n_in,
                              void* d_out, int out_size) {
    const float* values  = (const float*)d_in[0];
    const float* ln_in_g = (const float*)d_in[1];
    const float* ln_in_b = (const float*)d_in[2];
    const float* W_ga    = (const float*)d_in[3];
    const float* b_ga    = (const float*)d_in[4];
    const float* W_la    = (const float*)d_in[5];
    const float* b_la    = (const float*)d_in[6];
    const float* W_gb    = (const float*)d_in[7];
    const float* b_gb    = (const float*)d_in[8];
    const float* W_lb    = (const float*)d_in[9];
    const float* b_lb    = (const float*)d_in[10];
    const float* ln_o_g  = (const float*)d_in[11];
    const float* ln_o_b  = (const float*)d_in[12];
    const float* W_go    = (const float*)d_in[13];
    const float* b_go    = (const float*)d_in[14];
    const float* W_lo    = (const float*)d_in[15];
    const float* b_lo    = (const float*)d_in[16];
    // d_in[17] = indices (unused by the reference)
    float* out = (float*)d_out;

    int pack_threads = NOUT * CIN + CCH * CIN;   // 229376
    k_pack<<<(pack_threads + 255) / 256, 256>>>(W_ga, b_ga, W_la, b_la,
                                                W_gb, b_gb, W_lb, b_lb,
                                                W_go, b_go, W_lo);
    k_ln<<<NNZ / 8, 256>>>(values, ln_in_g, ln_in_b);
    k_gemm768<<<dim3(NRB, 12), 256>>>();
    k_epi1<<<NRB, 256>>>();
    k_redB<<<6, 256>>>();
    k_tri_ln<<<NNZ / 8, 256>>>(ln_o_g, ln_o_b);
    k_gemm256<<<dim3(NRB, 4), 256>>>(b_lo, out);
}

// round 4
// speedup vs baseline: 1.7496x; 1.7496x over previous
#include <cuda_runtime.h>
#include <cuda_bf16.h>
#include <math.h>
#include <stdint.h>

// ---------------- problem constants ----------------
#define NNZ    240000
#define CIN    256
#define CCH    128
#define KGRP   12
#define MT     128                 // rows per block tile
#define NRB1   (NNZ / MT)          // 1875
#define ASTRIDE 112                // bytes per A row in smem (56 bf16) — conflict-free ldmatrix

// ---------------- device scratch ----------------
__device__ __align__(16) uint32_t g_Wfh[6 * 16 * 16 * 64];   // big-GEMM B frags hi (393 KB)
__device__ __align__(16) uint32_t g_Wfl[6 * 16 * 16 * 64];
__device__ __align__(16) uint32_t g_W2h[2 * 8 * 16 * 64];    // out-GEMM B frags hi (65.5 KB)
__device__ __align__(16) uint32_t g_W2l[2 * 8 * 16 * 64];
__device__ float g_bcat[768];                                 // pair-interleaved bias
__device__ __align__(16) __nv_bfloat16 g_xh[(size_t)NNZ * CIN];
__device__ __align__(16) __nv_bfloat16 g_xl[(size_t)NNZ * CIN];
__device__ __align__(16) __nv_bfloat16 g_th[(size_t)NNZ * CCH];
__device__ __align__(16) __nv_bfloat16 g_tl[(size_t)NNZ * CCH];
__device__ float g_a[(size_t)NNZ * CCH];
__device__ float g_gate[(size_t)NNZ * CIN];
__device__ float g_Bpart[(size_t)NRB1 * KGRP * CCH];
__device__ float g_B[KGRP * CCH];

__device__ __forceinline__ float sigf(float x) { return 1.0f / (1.0f + expf(-x)); }

__device__ __forceinline__ uint32_t smem_u32(const void* p) {
    uint32_t a;
    asm("{ .reg .u64 t; cvta.to.shared.u64 t, %1; cvt.u32.u64 %0, t; }" : "=r"(a) : "l"(p));
    return a;
}
__device__ __forceinline__ void ldm_x4(uint32_t* r, uint32_t addr) {
    asm volatile("ldmatrix.sync.aligned.m8n8.x4.shared.b16 {%0,%1,%2,%3}, [%4];"
        : "=r"(r[0]), "=r"(r[1]), "=r"(r[2]), "=r"(r[3]) : "r"(addr));
}
__device__ __forceinline__ void mma_bf16(float* d, const uint32_t* a, uint32_t b0, uint32_t b1) {
    asm volatile("mma.sync.aligned.m16n8k16.row.col.f32.bf16.bf16.f32 "
        "{%0,%1,%2,%3}, {%4,%5,%6,%7}, {%8,%9}, {%0,%1,%2,%3};"
        : "+f"(d[0]), "+f"(d[1]), "+f"(d[2]), "+f"(d[3])
        : "r"(a[0]), "r"(a[1]), "r"(a[2]), "r"(a[3]), "r"(b0), "r"(b1));
}
__device__ __forceinline__ uint32_t pk(float a, float b) {
    return (uint32_t)__bfloat16_as_ushort(__float2bfloat16(a))
         | ((uint32_t)__bfloat16_as_ushort(__float2bfloat16(b)) << 16);
}
__device__ __forceinline__ float bfh(float x) {    // bf16-rounded value
    return __bfloat162float(__float2bfloat16(x));
}

// ---------------- kernel: pack weights into fragment-ordered hi/lo ----------------
// big GEMM packed col p: [0,256)=pair-interleave ga/la (even=gate), [256,512)=gb/lb, [512,768)=go
// fragment entry idx = ((nt*16+kb)*16+nb)*64 + lane*2 + reg; halves = k even/odd
__global__ void k_pack(const float* __restrict__ Wga, const float* __restrict__ bga,
                       const float* __restrict__ Wla, const float* __restrict__ bla,
                       const float* __restrict__ Wgb, const float* __restrict__ bgb,
                       const float* __restrict__ Wlb, const float* __restrict__ blb,
                       const float* __restrict__ Wgo, const float* __restrict__ bgo,
                       const float* __restrict__ Wlo) {
    int idx = blockIdx.x * blockDim.x + threadIdx.x;
    if (idx < 98304) {
        int lane2 = idx & 63, lane = lane2 >> 1, reg = lane2 & 1;
        int nb = (idx >> 6) & 15, kb = (idx >> 10) & 15, nt = idx >> 14;
        int k0 = kb * 16 + (lane & 3) * 2 + reg * 8;
        int p  = nt * 128 + nb * 8 + (lane >> 2);
        const float* W; int c;
        if (p < 256)      { c = p >> 1;               W = (p & 1) ? Wla : Wga; }
        else if (p < 512) { int q = p - 256; c = q >> 1; W = (q & 1) ? Wlb : Wgb; }
        else              { c = p - 512;              W = Wgo; }
        float w0 = W[c * CIN + k0], w1 = W[c * CIN + k0 + 1];
        float h0 = bfh(w0), h1 = bfh(w1);
        g_Wfh[idx] = pk(h0, h1);
        g_Wfl[idx] = pk(w0 - h0, w1 - h1);
    } else if (idx < 98304 + 16384) {
        int i2 = idx - 98304;
        int lane2 = i2 & 63, lane = lane2 >> 1, reg = lane2 & 1;
        int nb = (i2 >> 6) & 15, kb = (i2 >> 10) & 7, nt = i2 >> 13;
        int k0 = kb * 16 + (lane & 3) * 2 + reg * 8;   // [0,128)
        int j  = nt * 128 + nb * 8 + (lane >> 2);       // [0,256)
        float w0 = Wlo[j * CCH + k0], w1 = Wlo[j * CCH + k0 + 1];
        float h0 = bfh(w0), h1 = bfh(w1);
        g_W2h[i2] = pk(h0, h1);
        g_W2l[i2] = pk(w0 - h0, w1 - h1);
    } else if (idx < 98304 + 16384 + 768) {
        int p = idx - 98304 - 16384;
        float b;
        if (p < 256)      b = (p & 1) ? bla[p >> 1] : bga[p >> 1];
        else if (p < 512) { int q = p - 256; b = (q & 1) ? blb[q >> 1] : bgb[q >> 1]; }
        else              b = bgo[p - 512];
        g_bcat[p] = b;
    }
}

// ---------------- kernel: input layernorm -> bf16 hi/lo ----------------
__global__ void k_ln(const float* __restrict__ v,
                     const float* __restrict__ g, const float* __restrict__ b) {
    int row  = blockIdx.x * 8 + (threadIdx.x >> 5);
    int lane = threadIdx.x & 31;
    const float* vr = v + (size_t)row * CIN;
    float4 x0 = *(const float4*)(vr + lane * 4);
    float4 x1 = *(const float4*)(vr + 128 + lane * 4);
    float s = x0.x + x0.y + x0.z + x0.w + x1.x + x1.y + x1.z + x1.w;
    float q = x0.x*x0.x + x0.y*x0.y + x0.z*x0.z + x0.w*x0.w
            + x1.x*x1.x + x1.y*x1.y + x1.z*x1.z + x1.w*x1.w;
    #pragma unroll
    for (int o = 16; o; o >>= 1) {
        s += __shfl_xor_sync(0xffffffffu, s, o);
        q += __shfl_xor_sync(0xffffffffu, q, o);
    }
    float mu  = s * (1.0f / 256.0f);
    float var = fmaxf(q * (1.0f / 256.0f) - mu * mu, 0.0f);
    float rs  = rsqrtf(var + 1e-5f);
    float4 g0 = *(const float4*)(g + lane * 4);
    float4 g1 = *(const float4*)(g + 128 + lane * 4);
    float4 b0 = *(const float4*)(b + lane * 4);
    float4 b1 = *(const float4*)(b + 128 + lane * 4);
    float x[8];
    x[0]=(x0.x-mu)*rs*g0.x+b0.x; x[1]=(x0.y-mu)*rs*g0.y+b0.y;
    x[2]=(x0.z-mu)*rs*g0.z+b0.z; x[3]=(x0.w-mu)*rs*g0.w+b0.w;
    x[4]=(x1.x-mu)*rs*g1.x+b1.x; x[5]=(x1.y-mu)*rs*g1.y+b1.y;
    x[6]=(x1.z-mu)*rs*g1.z+b1.z; x[7]=(x1.w-mu)*rs*g1.w+b1.w;
    float h[8];
    #pragma unroll
    for (int e = 0; e < 8; ++e) h[e] = bfh(x[e]);
    __nv_bfloat16* ph = g_xh + (size_t)row * CIN;
    __nv_bfloat16* pl = g_xl + (size_t)row * CIN;
    *(uint2*)(ph + lane * 4)       = make_uint2(pk(h[0], h[1]), pk(h[2], h[3]));
    *(uint2*)(ph + 128 + lane * 4) = make_uint2(pk(h[4], h[5]), pk(h[6], h[7]));
    *(uint2*)(pl + lane * 4)       = make_uint2(pk(x[0]-h[0], x[1]-h[1]), pk(x[2]-h[2], x[3]-h[3]));
    *(uint2*)(pl + 128 + lane * 4) = make_uint2(pk(x[4]-h[4], x[5]-h[5]), pk(x[6]-h[6], x[7]-h[7]));
}

// ---------------- kernel: big fused GEMM (M=240000, N=768, K=256) ----------------
// grid (1875, 6); block 256 = 8 warps: wm = wid>>1 (m 32-slice), wn = wid&1 (n 64-slice)
__global__ void k_mma768() {
    __shared__ __align__(16) char Ash[MT * ASTRIDE];
    __shared__ __align__(16) char Asl[MT * ASTRIDE];
    __shared__ __align__(16) uint32_t sBh[16 * 64];
    __shared__ __align__(16) uint32_t sBl[16 * 64];
    __shared__ float sBp[KGRP * CCH];

    const int tid  = threadIdx.x;
    const int lane = tid & 31;
    const int wid  = tid >> 5;
    const int wm   = wid >> 1;
    const int wn   = wid & 1;
    const int nt   = blockIdx.y;
    const size_t row0 = (size_t)blockIdx.x * MT;

    for (int i = tid; i < KGRP * CCH; i += 256) sBp[i] = 0.0f;

    float acc[2][8][4];
    #pragma unroll
    for (int mb = 0; mb < 2; ++mb)
        #pragma unroll
        for (int nb = 0; nb < 8; ++nb)
            #pragma unroll
            for (int e = 0; e < 4; ++e) acc[mb][nb][e] = 0.0f;

    const uint32_t ash = smem_u32(Ash);
    const uint32_t asl = smem_u32(Asl);
    // ldmatrix per-lane row/col offsets
    const int lrow = (lane & 7) + ((lane >> 3) & 1) * 8;
    const int lkof = ((lane >> 4) & 1) * 16;   // bytes (8 bf16)

    for (int kc = 0; kc < 8; ++kc) {
        __syncthreads();
        // stage A chunk (128 rows x 32 k) hi/lo
        {
            int m = tid >> 2, qd = (tid & 3) * 16;   // byte col
            const uint4* srch = (const uint4*)(g_xh + (row0 + m) * CIN + kc * 32) + (tid & 3);
            const uint4* srcl = (const uint4*)(g_xl + (row0 + m) * CIN + kc * 32) + (tid & 3);
            *(uint4*)(Ash + m * ASTRIDE + qd) = *srch;
            *(uint4*)(Asl + m * ASTRIDE + qd) = *srcl;
            m += 64;
            srch = (const uint4*)(g_xh + (row0 + m) * CIN + kc * 32) + (tid & 3);
            srcl = (const uint4*)(g_xl + (row0 + m) * CIN + kc * 32) + (tid & 3);
            *(uint4*)(Ash + m * ASTRIDE + qd) = *srch;
            *(uint4*)(Asl + m * ASTRIDE + qd) = *srcl;
        }
        #pragma unroll
        for (int k2 = 0; k2 < 2; ++k2) {
            __syncthreads();
            // stage B fragments for this k16 (16 n-blocks x 64 u32, hi+lo)
            {
                int kbg = kc * 2 + k2;
                const uint4* sh = (const uint4*)(g_Wfh + (nt * 16 + kbg) * 1024);
                const uint4* sl = (const uint4*)(g_Wfl + (nt * 16 + kbg) * 1024);
                ((uint4*)sBh)[tid] = sh[tid];
                ((uint4*)sBl)[tid] = sl[tid];
            }
            __syncthreads();
            // A fragments for this warp's two m16 blocks
            uint32_t ah[2][4], al[2][4];
            #pragma unroll
            for (int mb = 0; mb < 2; ++mb) {
                uint32_t off = (uint32_t)((wm * 32 + mb * 16 + lrow) * ASTRIDE + k2 * 32 + lkof);
                ldm_x4(ah[mb], ash + off);
                ldm_x4(al[mb], asl + off);
            }
            const uint2* bh2 = (const uint2*)sBh;
            const uint2* bl2 = (const uint2*)sBl;
            #pragma unroll
            for (int nb = 0; nb < 8; ++nb) {
                int nbg = wn * 8 + nb;
                uint2 bh = bh2[nbg * 32 + lane];
                uint2 bl = bl2[nbg * 32 + lane];
                mma_bf16(acc[0][nb], ah[0], bh.x, bh.y);
                mma_bf16(acc[1][nb], ah[1], bh.x, bh.y);
                mma_bf16(acc[0][nb], ah[0], bl.x, bl.y);
                mma_bf16(acc[1][nb], ah[1], bl.x, bl.y);
                mma_bf16(acc[0][nb], al[0], bh.x, bh.y);
                mma_bf16(acc[1][nb], al[1], bh.x, bh.y);
            }
        }
    }

    // ---------------- fused epilogue ----------------
    const int cls0 = (int)(row0 % KGRP);
    #pragma unroll
    for (int mb = 0; mb < 2; ++mb) {
        #pragma unroll
        for (int nb = 0; nb < 8; ++nb) {
            int cloc = wn * 64 + nb * 8 + (lane & 3) * 2;     // n within 128-tile (even)
            float2 bias = *(const float2*)(g_bcat + nt * 128 + cloc);
            int lr0 = wm * 32 + mb * 16 + (lane >> 2);
            size_t r0 = row0 + lr0, r1 = r0 + 8;
            float y0 = acc[mb][nb][0] + bias.x;
            float y1 = acc[mb][nb][1] + bias.y;
            float y2 = acc[mb][nb][2] + bias.x;
            float y3 = acc[mb][nb][3] + bias.y;
            if (nt < 2) {
                int ch = nt * 64 + (cloc >> 1);
                g_a[r0 * CCH + ch] = sigf(y0) * y1;
                g_a[r1 * CCH + ch] = sigf(y2) * y3;
            } else if (nt < 4) {
                int ch = (nt - 2) * 64 + (cloc >> 1);
                int c0 = (cls0 + lr0) % KGRP;
                int c1 = (cls0 + lr0 + 8) % KGRP;
                atomicAdd(&sBp[c0 * CCH + ch], sigf(y0) * y1);
                atomicAdd(&sBp[c1 * CCH + ch], sigf(y2) * y3);
            } else {
                int cg = (nt - 4) * 128 + cloc;
                *(float2*)(g_gate + r0 * CIN + cg) = make_float2(sigf(y0), sigf(y1));
                *(float2*)(g_gate + r1 * CIN + cg) = make_float2(sigf(y2), sigf(y3));
            }
        }
    }
    if (blockIdx.y == 2 || blockIdx.y == 3) {
        __syncthreads();
        int half = (nt - 2) * 64;
        for (int t = tid; t < KGRP * 64; t += 256) {
            int cls = t >> 6, ch = (t & 63) + half;
            g_Bpart[(size_t)blockIdx.x * (KGRP * CCH) + cls * CCH + ch] = sBp[cls * CCH + ch];
        }
    }
}

// ---------------- kernel: reduce B partials (deterministic) ----------------
__global__ void k_redB() {
    int d = blockIdx.x * 256 + threadIdx.x;   // 0..1535
    float s = 0.0f;
    for (int b = 0; b < NRB1; ++b) s += g_Bpart[(size_t)b * (KGRP * CCH) + d];
    g_B[d] = s;
}

// ---------------- kernel: tri = a * B[row%12], LN(128) -> bf16 hi/lo ----------------
__global__ void k_tri_ln(const float* __restrict__ g, const float* __restrict__ b) {
    int row  = blockIdx.x * 8 + (threadIdx.x >> 5);
    int lane = threadIdx.x & 31;
    float4 av = *(const float4*)(g_a + (size_t)row * CCH + lane * 4);
    const float* Br = g_B + (row % KGRP) * CCH;
    float4 bv = *(const float4*)(Br + lane * 4);
    float t0 = av.x * bv.x, t1 = av.y * bv.y, t2 = av.z * bv.z, t3 = av.w * bv.w;
    float s = t0 + t1 + t2 + t3;
    float q = t0*t0 + t1*t1 + t2*t2 + t3*t3;
    #pragma unroll
    for (int o = 16; o; o >>= 1) {
        s += __shfl_xor_sync(0xffffffffu, s, o);
        q += __shfl_xor_sync(0xffffffffu, q, o);
    }
    float mu  = s * (1.0f / 128.0f);
    float var = fmaxf(q * (1.0f / 128.0f) - mu * mu, 0.0f);
    float rs  = rsqrtf(var + 1e-5f);
    float4 g4 = *(const float4*)(g + lane * 4);
    float4 b4 = *(const float4*)(b + lane * 4);
    float x0 = (t0 - mu) * rs * g4.x + b4.x;
    float x1 = (t1 - mu) * rs * g4.y + b4.y;
    float x2 = (t2 - mu) * rs * g4.z + b4.z;
    float x3 = (t3 - mu) * rs * g4.w + b4.w;
    float h0 = bfh(x0), h1 = bfh(x1), h2 = bfh(x2), h3 = bfh(x3);
    *(uint2*)(g_th + (size_t)row * CCH + lane * 4) = make_uint2(pk(h0, h1), pk(h2, h3));
    *(uint2*)(g_tl + (size_t)row * CCH + lane * 4) = make_uint2(pk(x0-h0, x1-h1), pk(x2-h2, x3-h3));
}

// ---------------- kernel: out = gate * (LN(tri) @ Wlo^T + b_lo)  (N=256, K=128) ----------------
__global__ void k_gemm256(const float* __restrict__ blo, float* __restrict__ out) {
    __shared__ __align__(16) char Ash[MT * ASTRIDE];
    __shared__ __align__(16) char Asl[MT * ASTRIDE];
    __shared__ __align__(16) uint32_t sBh[16 * 64];
    __shared__ __align__(16) uint32_t sBl[16 * 64];

    const int tid  = threadIdx.x;
    const int lane = tid & 31;
    const int wid  = tid >> 5;
    const int wm   = wid >> 1;
    const int wn   = wid & 1;
    const int nt   = blockIdx.y;
    const size_t row0 = (size_t)blockIdx.x * MT;

    float acc[2][8][4];
    #pragma unroll
    for (int mb = 0; mb < 2; ++mb)
        #pragma unroll
        for (int nb = 0; nb < 8; ++nb)
            #pragma unroll
            for (int e = 0; e < 4; ++e) acc[mb][nb][e] = 0.0f;

    const uint32_t ash = smem_u32(Ash);
    const uint32_t asl = smem_u32(Asl);
    const int lrow = (lane & 7) + ((lane >> 3) & 1) * 8;
    const int lkof = ((lane >> 4) & 1) * 16;

    for (int kc = 0; kc < 4; ++kc) {
        __syncthreads();
        {
            int m = tid >> 2, qd = (tid & 3) * 16;
            const uint4* srch = (const uint4*)(g_th + (row0 + m) * CCH + kc * 32) + (tid & 3);
            const uint4* srcl = (const uint4*)(g_tl + (row0 + m) * CCH + kc * 32) + (tid & 3);
            *(uint4*)(Ash + m * ASTRIDE + qd) = *srch;
            *(uint4*)(Asl + m * ASTRIDE + qd) = *srcl;
            m += 64;
            srch = (const uint4*)(g_th + (row0 + m) * CCH + kc * 32) + (tid & 3);
            srcl = (const uint4*)(g_tl + (row0 + m) * CCH + kc * 32) + (tid & 3);
            *(uint4*)(Ash + m * ASTRIDE + qd) = *srch;
            *(uint4*)(Asl + m * ASTRIDE + qd) = *srcl;
        }
        #pragma unroll
        for (int k2 = 0; k2 < 2; ++k2) {
            __syncthreads();
            {
                int kbg = kc * 2 + k2;
                const uint4* sh = (const uint4*)(g_W2h + (nt * 8 + kbg) * 1024);
                const uint4* sl = (const uint4*)(g_W2l + (nt * 8 + kbg) * 1024);
                ((uint4*)sBh)[tid] = sh[tid];
                ((uint4*)sBl)[tid] = sl[tid];
            }
            __syncthreads();
            uint32_t ah[2][4], al[2][4];
            #pragma unroll
            for (int mb = 0; mb < 2; ++mb) {
                uint32_t off = (uint32_t)((wm * 32 + mb * 16 + lrow) * ASTRIDE + k2 * 32 + lkof);
                ldm_x4(ah[mb], ash + off);
                ldm_x4(al[mb], asl + off);
            }
            const uint2* bh2 = (const uint2*)sBh;
            const uint2* bl2 = (const uint2*)sBl;
            #pragma unroll
            for (int nb = 0; nb < 8; ++nb) {
                int nbg = wn * 8 + nb;
                uint2 bh = bh2[nbg * 32 + lane];
                uint2 bl = bl2[nbg * 32 + lane];
                mma_bf16(acc[0][nb], ah[0], bh.x, bh.y);
                mma_bf16(acc[1][nb], ah[1], bh.x, bh.y);
                mma_bf16(acc[0][nb], ah[0], bl.x, bl.y);
                mma_bf16(acc[1][nb], ah[1], bl.x, bl.y);
                mma_bf16(acc[0][nb], al[0], bh.x, bh.y);
                mma_bf16(acc[1][nb], al[1], bh.x, bh.y);
            }
        }
    }

    #pragma unroll
    for (int mb = 0; mb < 2; ++mb) {
        #pragma unroll
        for (int nb = 0; nb < 8; ++nb) {
            int c = nt * 128 + wn * 64 + nb * 8 + (lane & 3) * 2;
            float2 bias = *(const float2*)(blo + c);
            size_t r0 = row0 + wm * 32 + mb * 16 + (lane >> 2), r1 = r0 + 8;
            float2 gt0 = *(const float2*)(g_gate + r0 * CIN + c);
            float2 gt1 = *(const float2*)(g_gate + r1 * CIN + c);
            float2 o0 = make_float2(gt0.x * (acc[mb][nb][0] + bias.x),
                                    gt0.y * (acc[mb][nb][1] + bias.y));
            float2 o1 = make_float2(gt1.x * (acc[mb][nb][2] + bias.x),
                                    gt1.y * (acc[mb][nb][3] + bias.y));
            *(float2*)(out + r0 * CIN + c) = o0;
            *(float2*)(out + r1 * CIN + c) = o1;
        }
    }
}

// ---------------- launch ----------------
extern "C" void kernel_launch(void* const* d_in, const int* in_sizes, int n_in,
                              void* d_out, int out_size) {
    const float* values  = (const float*)d_in[0];
    const float* ln_in_g = (const float*)d_in[1];
    const float* ln_in_b = (const float*)d_in[2];
    const float* W_ga    = (const float*)d_in[3];
    const float* b_ga    = (const float*)d_in[4];
    const float* W_la    = (const float*)d_in[5];
    const float* b_la    = (const float*)d_in[6];
    const float* W_gb    = (const float*)d_in[7];
    const float* b_gb    = (const float*)d_in[8];
    const float* W_lb    = (const float*)d_in[9];
    const float* b_lb    = (const float*)d_in[10];
    const float* ln_o_g  = (const float*)d_in[11];
    const float* ln_o_b  = (const float*)d_in[12];
    const float* W_go    = (const float*)d_in[13];
    const float* b_go    = (const float*)d_in[14];
    const float* W_lo    = (const float*)d_in[15];
    const float* b_lo    = (const float*)d_in[16];
    float* out = (float*)d_out;

    int pack_threads = 98304 + 16384 + 768;
    k_pack<<<(pack_threads + 255) / 256, 256>>>(W_ga, b_ga, W_la, b_la,
                                                W_gb, b_gb, W_lb, b_lb,
                                                W_go, b_go, W_lo);
    k_ln<<<NNZ / 8, 256>>>(values, ln_in_g, ln_in_b);
    k_mma768<<<dim3(NRB1, 6), 256>>>();
    k_redB<<<6, 256>>>();
    k_tri_ln<<<NNZ / 8, 256>>>(ln_o_g, ln_o_b);
    k_gemm256<<<dim3(NRB1, 2), 256>>>(b_lo, out);
}

// round 5
// speedup vs baseline: 2.6082x; 1.4907x over previous
#include <cuda_runtime.h>
#include <cuda_bf16.h>
#include <math.h>
#include <stdint.h>

// ---------------- problem constants ----------------
#define NNZ   240000
#define CIN   256
#define CCH   128
#define KGRP  12
#define MT    128
#define NRB1  (NNZ / MT)          // 1875

#define AS1   528                 // A smem row stride bytes (K=256 bf16 + 16B pad)
#define AS2   272                 // K=128 bf16 + 16B pad

// smem layout k_mma1 (bytes)
#define SM1_ASL   (128 * AS1)
#define SM1_BP    (2 * 128 * AS1)
#define SM1_BIAS  (SM1_BP + KGRP * CCH * 4)
#define SM1_TOTAL (SM1_BIAS + 768 * 4)      // 144384
// smem layout k_mma2
#define SM2_ASL   (128 * AS2)
#define SM2_B     (2 * 128 * AS2)
#define SM2_TOTAL (SM2_B + KGRP * CCH * 4)  // 75776

// ---------------- device scratch ----------------
__device__ __align__(16) uint32_t g_Wfh[6 * 16 * 16 * 64];   // big-GEMM B frags hi
__device__ __align__(16) uint32_t g_Wfl[6 * 16 * 16 * 64];
__device__ __align__(16) uint32_t g_W2h[2 * 8 * 16 * 64];    // out-GEMM B frags hi
__device__ __align__(16) uint32_t g_W2l[2 * 8 * 16 * 64];
__device__ float g_bcat[768];                                // pair-interleaved bias
__device__ float g_a[(size_t)NNZ * CCH];
__device__ float g_gate[(size_t)NNZ * CIN];
__device__ float g_Bpart[(size_t)NRB1 * KGRP * CCH];
__device__ float g_B2[25 * KGRP * CCH];
__device__ float g_B[KGRP * CCH];

__device__ __forceinline__ float sigf(float x) { return 1.0f / (1.0f + expf(-x)); }

__device__ __forceinline__ uint32_t smem_u32(const void* p) {
    uint32_t a;
    asm("{ .reg .u64 t; cvta.to.shared.u64 t, %1; cvt.u32.u64 %0, t; }" : "=r"(a) : "l"(p));
    return a;
}
__device__ __forceinline__ void ldm_x4(uint32_t* r, uint32_t addr) {
    asm volatile("ldmatrix.sync.aligned.m8n8.x4.shared.b16 {%0,%1,%2,%3}, [%4];"
        : "=r"(r[0]), "=r"(r[1]), "=r"(r[2]), "=r"(r[3]) : "r"(addr));
}
__device__ __forceinline__ void mma_bf16(float* d, const uint32_t* a, uint32_t b0, uint32_t b1) {
    asm volatile("mma.sync.aligned.m16n8k16.row.col.f32.bf16.bf16.f32 "
        "{%0,%1,%2,%3}, {%4,%5,%6,%7}, {%8,%9}, {%0,%1,%2,%3};"
        : "+f"(d[0]), "+f"(d[1]), "+f"(d[2]), "+f"(d[3])
        : "r"(a[0]), "r"(a[1]), "r"(a[2]), "r"(a[3]), "r"(b0), "r"(b1));
}
__device__ __forceinline__ uint32_t pk(float a, float b) {
    return (uint32_t)__bfloat16_as_ushort(__float2bfloat16(a))
         | ((uint32_t)__bfloat16_as_ushort(__float2bfloat16(b)) << 16);
}
__device__ __forceinline__ float bfh(float x) {
    return __bfloat162float(__float2bfloat16(x));
}

// ---------------- kernel: pack weights into fragment-ordered hi/lo ----------------
// packed col p: [0,256)=pair-interleave ga/la (even=gate), [256,512)=gb/lb, [512,768)=go
// frag idx = ((nt*16+kb)*16+nb)*64 + lane*2 + reg
__global__ void k_pack(const float* __restrict__ Wga, const float* __restrict__ bga,
                       const float* __restrict__ Wla, const float* __restrict__ bla,
                       const float* __restrict__ Wgb, const float* __restrict__ bgb,
                       const float* __restrict__ Wlb, const float* __restrict__ blb,
                       const float* __restrict__ Wgo, const float* __restrict__ bgo,
                       const float* __restrict__ Wlo) {
    int idx = blockIdx.x * blockDim.x + threadIdx.x;
    if (idx < 98304) {
        int lane2 = idx & 63, lane = lane2 >> 1, reg = lane2 & 1;
        int nb = (idx >> 6) & 15, kb = (idx >> 10) & 15, nt = idx >> 14;
        int k0 = kb * 16 + (lane & 3) * 2 + reg * 8;
        int p  = nt * 128 + nb * 8 + (lane >> 2);
        const float* W; int c;
        if (p < 256)      { c = p >> 1;                W = (p & 1) ? Wla : Wga; }
        else if (p < 512) { int q = p - 256; c = q >> 1; W = (q & 1) ? Wlb : Wgb; }
        else              { c = p - 512;               W = Wgo; }
        float w0 = W[c * CIN + k0], w1 = W[c * CIN + k0 + 1];
        float h0 = bfh(w0), h1 = bfh(w1);
        g_Wfh[idx] = pk(h0, h1);
        g_Wfl[idx] = pk(w0 - h0, w1 - h1);
    } else if (idx < 98304 + 16384) {
        int i2 = idx - 98304;
        int lane2 = i2 & 63, lane = lane2 >> 1, reg = lane2 & 1;
        int nb = (i2 >> 6) & 15, kb = (i2 >> 10) & 7, nt = i2 >> 13;
        int k0 = kb * 16 + (lane & 3) * 2 + reg * 8;
        int j  = nt * 128 + nb * 8 + (lane >> 2);
        float w0 = Wlo[j * CCH + k0], w1 = Wlo[j * CCH + k0 + 1];
        float h0 = bfh(w0), h1 = bfh(w1);
        g_W2h[i2] = pk(h0, h1);
        g_W2l[i2] = pk(w0 - h0, w1 - h1);
    } else if (idx < 98304 + 16384 + 768) {
        int p = idx - 98304 - 16384;
        float b;
        if (p < 256)      b = (p & 1) ? bla[p >> 1] : bga[p >> 1];
        else if (p < 512) { int q = p - 256; b = (q & 1) ? blb[q >> 1] : bgb[q >> 1]; }
        else              b = bgo[p - 512];
        g_bcat[p] = b;
    }
}

// ---------------- kernel 1: LN + big GEMM (768 cols) + fused epilogues ----------------
// block = 128 rows; warps: wm = wid>>2 (m 64-slice), wn = wid&3 (n 32-slice)
__global__ void __launch_bounds__(256, 1)
k_mma1(const float* __restrict__ vals,
       const float* __restrict__ lng, const float* __restrict__ lnb) {
    extern __shared__ char sm[];
    char*  Ash   = sm;
    char*  Asl   = sm + SM1_ASL;
    float* sBp   = (float*)(sm + SM1_BP);
    float* sbias = (float*)(sm + SM1_BIAS);

    const int tid  = threadIdx.x;
    const int lane = tid & 31;
    const int wid  = tid >> 5;
    const int wm   = wid >> 2;
    const int wn   = wid & 3;
    const size_t row0 = (size_t)blockIdx.x * MT;

    for (int i = tid; i < KGRP * CCH; i += 256) sBp[i] = 0.0f;
    for (int i = tid; i < 768; i += 256) sbias[i] = g_bcat[i];

    // ---- LN phase: 16 rows per warp, split hi/lo into smem A image ----
    {
        float4 g0 = *(const float4*)(lng + lane * 4);
        float4 g1 = *(const float4*)(lng + 128 + lane * 4);
        float4 b0 = *(const float4*)(lnb + lane * 4);
        float4 b1 = *(const float4*)(lnb + 128 + lane * 4);
        for (int rr = 0; rr < 16; ++rr) {
            int r = wid * 16 + rr;
            const float* vr = vals + (row0 + r) * CIN;
            float4 v0 = *(const float4*)(vr + lane * 4);
            float4 v1 = *(const float4*)(vr + 128 + lane * 4);
            float s = v0.x + v0.y + v0.z + v0.w + v1.x + v1.y + v1.z + v1.w;
            float q = v0.x*v0.x + v0.y*v0.y + v0.z*v0.z + v0.w*v0.w
                    + v1.x*v1.x + v1.y*v1.y + v1.z*v1.z + v1.w*v1.w;
            #pragma unroll
            for (int o = 16; o; o >>= 1) {
                s += __shfl_xor_sync(0xffffffffu, s, o);
                q += __shfl_xor_sync(0xffffffffu, q, o);
            }
            float mu  = s * (1.0f / 256.0f);
            float var = fmaxf(q * (1.0f / 256.0f) - mu * mu, 0.0f);
            float rs  = rsqrtf(var + 1e-5f);
            float x[8], h[8];
            x[0]=(v0.x-mu)*rs*g0.x+b0.x; x[1]=(v0.y-mu)*rs*g0.y+b0.y;
            x[2]=(v0.z-mu)*rs*g0.z+b0.z; x[3]=(v0.w-mu)*rs*g0.w+b0.w;
            x[4]=(v1.x-mu)*rs*g1.x+b1.x; x[5]=(v1.y-mu)*rs*g1.y+b1.y;
            x[6]=(v1.z-mu)*rs*g1.z+b1.z; x[7]=(v1.w-mu)*rs*g1.w+b1.w;
            #pragma unroll
            for (int e = 0; e < 8; ++e) h[e] = bfh(x[e]);
            *(uint2*)(Ash + r*AS1 + lane*8)       = make_uint2(pk(h[0],h[1]), pk(h[2],h[3]));
            *(uint2*)(Ash + r*AS1 + 256 + lane*8) = make_uint2(pk(h[4],h[5]), pk(h[6],h[7]));
            *(uint2*)(Asl + r*AS1 + lane*8)       = make_uint2(pk(x[0]-h[0],x[1]-h[1]), pk(x[2]-h[2],x[3]-h[3]));
            *(uint2*)(Asl + r*AS1 + 256 + lane*8) = make_uint2(pk(x[4]-h[4],x[5]-h[5]), pk(x[6]-h[6],x[7]-h[7]));
        }
    }
    __syncthreads();

    const uint32_t ash = smem_u32(Ash);
    const uint32_t asl = smem_u32(Asl);
    const int lrow = (lane & 7) + ((lane >> 3) & 1) * 8;
    const int lkof = ((lane >> 4) & 1) * 16;
    const uint32_t abase = (uint32_t)((wm * 64 + lrow) * AS1 + lkof);
    const int cls0 = (int)(row0 % KGRP);

    #pragma unroll 1
    for (int nt = 0; nt < 6; ++nt) {
        float acc[4][4][4];
        #pragma unroll
        for (int mb = 0; mb < 4; ++mb)
            #pragma unroll
            for (int nb = 0; nb < 4; ++nb)
                #pragma unroll
                for (int e = 0; e < 4; ++e) acc[mb][nb][e] = 0.0f;

        const uint2* __restrict__ BH = ((const uint2*)g_Wfh) + ((size_t)(nt*16)*16 + wn*4)*32 + lane;
        const uint2* __restrict__ BL = ((const uint2*)g_Wfl) + ((size_t)(nt*16)*16 + wn*4)*32 + lane;

        uint2 bh[2][4], bl[2][4];
        #pragma unroll
        for (int nb = 0; nb < 4; ++nb) {
            bh[0][nb] = BH[nb * 32];
            bl[0][nb] = BL[nb * 32];
        }
        #pragma unroll
        for (int kb = 0; kb < 16; ++kb) {
            const int cur = kb & 1, nxt = cur ^ 1;
            if (kb < 15) {
                #pragma unroll
                for (int nb = 0; nb < 4; ++nb) {
                    bh[nxt][nb] = BH[((kb + 1) * 16 + nb) * 32];
                    bl[nxt][nb] = BL[((kb + 1) * 16 + nb) * 32];
                }
            }
            uint32_t ah[4][4], al[4][4];
            #pragma unroll
            for (int mb = 0; mb < 4; ++mb) {
                uint32_t off = abase + mb * 16 * AS1 + kb * 32;
                ldm_x4(ah[mb], ash + off);
                ldm_x4(al[mb], asl + off);
            }
            #pragma unroll
            for (int nb = 0; nb < 4; ++nb) {
                #pragma unroll
                for (int mb = 0; mb < 4; ++mb) {
                    mma_bf16(acc[mb][nb], ah[mb], bh[cur][nb].x, bh[cur][nb].y);
                    mma_bf16(acc[mb][nb], ah[mb], bl[cur][nb].x, bl[cur][nb].y);
                    mma_bf16(acc[mb][nb], al[mb], bh[cur][nb].x, bh[cur][nb].y);
                }
            }
        }

        // ---- fused epilogue for this 128-col tile ----
        #pragma unroll
        for (int mb = 0; mb < 4; ++mb) {
            #pragma unroll
            for (int nb = 0; nb < 4; ++nb) {
                int cloc = (wn * 4 + nb) * 8 + (lane & 3) * 2;
                float bx = sbias[nt * 128 + cloc];
                float by = sbias[nt * 128 + cloc + 1];
                int lr0 = wm * 64 + mb * 16 + (lane >> 2);
                size_t r0 = row0 + lr0, r1 = r0 + 8;
                float y0 = acc[mb][nb][0] + bx;
                float y1 = acc[mb][nb][1] + by;
                float y2 = acc[mb][nb][2] + bx;
                float y3 = acc[mb][nb][3] + by;
                if (nt < 2) {
                    int ch = nt * 64 + (cloc >> 1);
                    g_a[r0 * CCH + ch] = sigf(y0) * y1;
                    g_a[r1 * CCH + ch] = sigf(y2) * y3;
                } else if (nt < 4) {
                    int ch = (nt - 2) * 64 + (cloc >> 1);
                    int c0 = (cls0 + lr0) % KGRP;
                    int c1 = (cls0 + lr0 + 8) % KGRP;
                    atomicAdd(&sBp[c0 * CCH + ch], sigf(y0) * y1);
                    atomicAdd(&sBp[c1 * CCH + ch], sigf(y2) * y3);
                } else {
                    int cg = (nt - 4) * 128 + cloc;
                    *(float2*)(g_gate + r0 * CIN + cg) = make_float2(sigf(y0), sigf(y1));
                    *(float2*)(g_gate + r1 * CIN + cg) = make_float2(sigf(y2), sigf(y3));
                }
            }
        }
    }
    __syncthreads();
    for (int i = tid; i < KGRP * CCH; i += 256)
        g_Bpart[(size_t)blockIdx.x * (KGRP * CCH) + i] = sBp[i];
}

// ---------------- reduce B partials: 2-stage, deterministic ----------------
__global__ void k_redB1() {          // grid (6, 25)
    int d = blockIdx.x * 256 + threadIdx.x;
    int b0 = blockIdx.y * 75;
    float s = 0.0f;
    for (int b = b0; b < b0 + 75; ++b) s += g_Bpart[(size_t)b * (KGRP * CCH) + d];
    g_B2[blockIdx.y * (KGRP * CCH) + d] = s;
}
__global__ void k_redB2() {          // grid 6
    int d = blockIdx.x * 256 + threadIdx.x;
    float s = 0.0f;
    for (int y = 0; y < 25; ++y) s += g_B2[y * (KGRP * CCH) + d];
    g_B[d] = s;
}

// ---------------- kernel 2: tri + LN + out GEMM (256 cols) + gate ----------------
__global__ void __launch_bounds__(256, 1)
k_mma2(const float* __restrict__ lnog, const float* __restrict__ lnob,
       const float* __restrict__ blo, float* __restrict__ out) {
    extern __shared__ char sm[];
    char*  Ash = sm;
    char*  Asl = sm + SM2_ASL;
    float* Bsm = (float*)(sm + SM2_B);

    const int tid  = threadIdx.x;
    const int lane = tid & 31;
    const int wid  = tid >> 5;
    const int wm   = wid >> 2;
    const int wn   = wid & 3;
    const size_t row0 = (size_t)blockIdx.x * MT;

    for (int i = tid; i < KGRP * CCH; i += 256) Bsm[i] = g_B[i];
    __syncthreads();

    // ---- tri = a * B[row%12], LN over 128, split hi/lo into smem ----
    {
        float4 g4 = *(const float4*)(lnog + lane * 4);
        float4 b4 = *(const float4*)(lnob + lane * 4);
        for (int rr = 0; rr < 16; ++rr) {
            int r = wid * 16 + rr;
            size_t gr = row0 + r;
            float4 av = *(const float4*)(g_a + gr * CCH + lane * 4);
            const float* Br = Bsm + (int)(gr % KGRP) * CCH;
            float4 bv = *(const float4*)(Br + lane * 4);
            float t0 = av.x*bv.x, t1 = av.y*bv.y, t2 = av.z*bv.z, t3 = av.w*bv.w;
            float s = t0 + t1 + t2 + t3;
            float q = t0*t0 + t1*t1 + t2*t2 + t3*t3;
            #pragma unroll
            for (int o = 16; o; o >>= 1) {
                s += __shfl_xor_sync(0xffffffffu, s, o);
                q += __shfl_xor_sync(0xffffffffu, q, o);
            }
            float mu  = s * (1.0f / 128.0f);
            float var = fmaxf(q * (1.0f / 128.0f) - mu * mu, 0.0f);
            float rs  = rsqrtf(var + 1e-5f);
            float x0 = (t0 - mu) * rs * g4.x + b4.x;
            float x1 = (t1 - mu) * rs * g4.y + b4.y;
            float x2 = (t2 - mu) * rs * g4.z + b4.z;
            float x3 = (t3 - mu) * rs * g4.w + b4.w;
            float h0 = bfh(x0), h1 = bfh(x1), h2 = bfh(x2), h3 = bfh(x3);
            *(uint2*)(Ash + r*AS2 + lane*8) = make_uint2(pk(h0,h1), pk(h2,h3));
            *(uint2*)(Asl + r*AS2 + lane*8) = make_uint2(pk(x0-h0,x1-h1), pk(x2-h2,x3-h3));
        }
    }
    __syncthreads();

    const uint32_t ash = smem_u32(Ash);
    const uint32_t asl = smem_u32(Asl);
    const int lrow = (lane & 7) + ((lane >> 3) & 1) * 8;
    const int lkof = ((lane >> 4) & 1) * 16;
    const uint32_t abase = (uint32_t)((wm * 64 + lrow) * AS2 + lkof);

    #pragma unroll 1
    for (int nt = 0; nt < 2; ++nt) {
        float acc[4][4][4];
        #pragma unroll
        for (int mb = 0; mb < 4; ++mb)
            #pragma unroll
            for (int nb = 0; nb < 4; ++nb)
                #pragma unroll
                for (int e = 0; e < 4; ++e) acc[mb][nb][e] = 0.0f;

        const uint2* __restrict__ BH = ((const uint2*)g_W2h) + ((size_t)(nt*8)*16 + wn*4)*32 + lane;
        const uint2* __restrict__ BL = ((const uint2*)g_W2l) + ((size_t)(nt*8)*16 + wn*4)*32 + lane;

        uint2 bh[2][4], bl[2][4];
        #pragma unroll
        for (int nb = 0; nb < 4; ++nb) {
            bh[0][nb] = BH[nb * 32];
            bl[0][nb] = BL[nb * 32];
        }
        #pragma unroll
        for (int kb = 0; kb < 8; ++kb) {
            const int cur = kb & 1, nxt = cur ^ 1;
            if (kb < 7) {
                #pragma unroll
                for (int nb = 0; nb < 4; ++nb) {
                    bh[nxt][nb] = BH[((kb + 1) * 16 + nb) * 32];
                    bl[nxt][nb] = BL[((kb + 1) * 16 + nb) * 32];
                }
            }
            uint32_t ah[4][4], al[4][4];
            #pragma unroll
            for (int mb = 0; mb < 4; ++mb) {
                uint32_t off = abase + mb * 16 * AS2 + kb * 32;
                ldm_x4(ah[mb], ash + off);
                ldm_x4(al[mb], asl + off);
            }
            #pragma unroll
            for (int nb = 0; nb < 4; ++nb) {
                #pragma unroll
                for (int mb = 0; mb < 4; ++mb) {
                    mma_bf16(acc[mb][nb], ah[mb], bh[cur][nb].x, bh[cur][nb].y);
                    mma_bf16(acc[mb][nb], ah[mb], bl[cur][nb].x, bl[cur][nb].y);
                    mma_bf16(acc[mb][nb], al[mb], bh[cur][nb].x, bh[cur][nb].y);
                }
            }
        }

        // ---- epilogue: out = gate * (acc + blo) ----
        #pragma unroll
        for (int mb = 0; mb < 4; ++mb) {
            #pragma unroll
            for (int nb = 0; nb < 4; ++nb) {
                int c = nt * 128 + (wn * 4 + nb) * 8 + (lane & 3) * 2;
                float2 bias = *(const float2*)(blo + c);
                size_t r0 = row0 + wm * 64 + mb * 16 + (lane >> 2), r1 = r0 + 8;
                float2 gt0 = *(const float2*)(g_gate + r0 * CIN + c);
                float2 gt1 = *(const float2*)(g_gate + r1 * CIN + c);
                *(float2*)(out + r0 * CIN + c) =
                    make_float2(gt0.x * (acc[mb][nb][0] + bias.x),
                                gt0.y * (acc[mb][nb][1] + bias.y));
                *(float2*)(out + r1 * CIN + c) =
                    make_float2(gt1.x * (acc[mb][nb][2] + bias.x),
                                gt1.y * (acc[mb][nb][3] + bias.y));
            }
        }
    }
}

// ---------------- launch ----------------
extern "C" void kernel_launch(void* const* d_in, const int* in_sizes, int n_in,
                              void* d_out, int out_size) {
    const float* values  = (const float*)d_in[0];
    const float* ln_in_g = (const float*)d_in[1];
    const float* ln_in_b = (const float*)d_in[2];
    const float* W_ga    = (const float*)d_in[3];
    const float* b_ga    = (const float*)d_in[4];
    const float* W_la    = (const float*)d_in[5];
    const float* b_la    = (const float*)d_in[6];
    const float* W_gb    = (const float*)d_in[7];
    const float* b_gb    = (const float*)d_in[8];
    const float* W_lb    = (const float*)d_in[9];
    const float* b_lb    = (const float*)d_in[10];
    const float* ln_o_g  = (const float*)d_in[11];
    const float* ln_o_b  = (const float*)d_in[12];
    const float* W_go    = (const float*)d_in[13];
    const float* b_go    = (const float*)d_in[14];
    const float* W_lo    = (const float*)d_in[15];
    const float* b_lo    = (const float*)d_in[16];
    float* out = (float*)d_out;

    cudaFuncSetAttribute(k_mma1, cudaFuncAttributeMaxDynamicSharedMemorySize, SM1_TOTAL);
    cudaFuncSetAttribute(k_mma2, cudaFuncAttributeMaxDynamicSharedMemorySize, SM2_TOTAL);

    int pack_threads = 98304 + 16384 + 768;
    k_pack<<<(pack_threads + 255) / 256, 256>>>(W_ga, b_ga, W_la, b_la,
                                                W_gb, b_gb, W_lb, b_lb,
                                                W_go, b_go, W_lo);
    k_mma1<<<NRB1, 256, SM1_TOTAL>>>(values, ln_in_g, ln_in_b);
    k_redB1<<<dim3(6, 25), 256>>>();
    k_redB2<<<6, 256>>>();
    k_mma2<<<NRB1, 256, SM2_TOTAL>>>(ln_o_g, ln_o_b, b_lo, out);
}

// round 6
// speedup vs baseline: 3.1361x; 1.2024x over previous
#include <cuda_runtime.h>
#include <cuda_bf16.h>
#include <math.h>
#include <stdint.h>

// ---------------- problem constants ----------------
#define NNZ   240000
#define CIN   256
#define CCH   128
#define KGRP  12
#define MT    128
#define NRB1  (NNZ / MT)          // 1875
#define NTHR  512

#define AS1   528                 // A smem row stride bytes (K=256 bf16 + 16B pad)
#define AS2   272                 // K=128 bf16 + 16B pad

// smem layout k_mma1 (bytes)
#define SM1_ASL   (128 * AS1)
#define SM1_BP    (2 * 128 * AS1)
#define SM1_BIAS  (SM1_BP + KGRP * CCH * 4)
#define SM1_TOTAL (SM1_BIAS + 768 * 4)      // 144384
// smem layout k_mma2
#define SM2_ASL   (128 * AS2)
#define SM2_B     (2 * 128 * AS2)
#define SM2_TOTAL (SM2_B + KGRP * CCH * 4)  // 75776

// ---------------- device scratch ----------------
__device__ __align__(16) uint32_t g_Wfh[6 * 16 * 16 * 64];   // big-GEMM B frags hi
__device__ __align__(16) uint32_t g_Wfl[6 * 16 * 16 * 64];
__device__ __align__(16) uint32_t g_W2h[2 * 8 * 16 * 64];    // out-GEMM B frags hi
__device__ __align__(16) uint32_t g_W2l[2 * 8 * 16 * 64];
__device__ float g_bcat[768];                                // pair-interleaved bias
__device__ float g_a[(size_t)NNZ * CCH];
__device__ float g_gate[(size_t)NNZ * CIN];
__device__ float g_Bpart[(size_t)NRB1 * KGRP * CCH];
__device__ float g_B2[25 * KGRP * CCH];
__device__ float g_B[KGRP * CCH];

__device__ __forceinline__ float sigf(float x) { return 1.0f / (1.0f + expf(-x)); }

__device__ __forceinline__ uint32_t smem_u32(const void* p) {
    uint32_t a;
    asm("{ .reg .u64 t; cvta.to.shared.u64 t, %1; cvt.u32.u64 %0, t; }" : "=r"(a) : "l"(p));
    return a;
}
__device__ __forceinline__ void ldm_x4(uint32_t* r, uint32_t addr) {
    asm volatile("ldmatrix.sync.aligned.m8n8.x4.shared.b16 {%0,%1,%2,%3}, [%4];"
        : "=r"(r[0]), "=r"(r[1]), "=r"(r[2]), "=r"(r[3]) : "r"(addr));
}
__device__ __forceinline__ void mma_bf16(float* d, const uint32_t* a, uint32_t b0, uint32_t b1) {
    asm volatile("mma.sync.aligned.m16n8k16.row.col.f32.bf16.bf16.f32 "
        "{%0,%1,%2,%3}, {%4,%5,%6,%7}, {%8,%9}, {%0,%1,%2,%3};"
        : "+f"(d[0]), "+f"(d[1]), "+f"(d[2]), "+f"(d[3])
        : "r"(a[0]), "r"(a[1]), "r"(a[2]), "r"(a[3]), "r"(b0), "r"(b1));
}
__device__ __forceinline__ uint32_t pk(float a, float b) {
    return (uint32_t)__bfloat16_as_ushort(__float2bfloat16(a))
         | ((uint32_t)__bfloat16_as_ushort(__float2bfloat16(b)) << 16);
}
__device__ __forceinline__ float bfh(float x) {
    return __bfloat162float(__float2bfloat16(x));
}

// ---------------- kernel: pack weights into fragment-ordered hi/lo ----------------
// packed col p: [0,256)=pair-interleave ga/la (even=gate), [256,512)=gb/lb, [512,768)=go
// frag idx = ((nt*16+kb)*16+nb)*64 + lane*2 + reg
__global__ void k_pack(const float* __restrict__ Wga, const float* __restrict__ bga,
                       const float* __restrict__ Wla, const float* __restrict__ bla,
                       const float* __restrict__ Wgb, const float* __restrict__ bgb,
                       const float* __restrict__ Wlb, const float* __restrict__ blb,
                       const float* __restrict__ Wgo, const float* __restrict__ bgo,
                       const float* __restrict__ Wlo) {
    int idx = blockIdx.x * blockDim.x + threadIdx.x;
    if (idx < 98304) {
        int lane2 = idx & 63, lane = lane2 >> 1, reg = lane2 & 1;
        int nb = (idx >> 6) & 15, kb = (idx >> 10) & 15, nt = idx >> 14;
        int k0 = kb * 16 + (lane & 3) * 2 + reg * 8;
        int p  = nt * 128 + nb * 8 + (lane >> 2);
        const float* W; int c;
        if (p < 256)      { c = p >> 1;                W = (p & 1) ? Wla : Wga; }
        else if (p < 512) { int q = p - 256; c = q >> 1; W = (q & 1) ? Wlb : Wgb; }
        else              { c = p - 512;               W = Wgo; }
        float w0 = W[c * CIN + k0], w1 = W[c * CIN + k0 + 1];
        float h0 = bfh(w0), h1 = bfh(w1);
        g_Wfh[idx] = pk(h0, h1);
        g_Wfl[idx] = pk(w0 - h0, w1 - h1);
    } else if (idx < 98304 + 16384) {
        int i2 = idx - 98304;
        int lane2 = i2 & 63, lane = lane2 >> 1, reg = lane2 & 1;
        int nb = (i2 >> 6) & 15, kb = (i2 >> 10) & 7, nt = i2 >> 13;
        int k0 = kb * 16 + (lane & 3) * 2 + reg * 8;
        int j  = nt * 128 + nb * 8 + (lane >> 2);
        float w0 = Wlo[j * CCH + k0], w1 = Wlo[j * CCH + k0 + 1];
        float h0 = bfh(w0), h1 = bfh(w1);
        g_W2h[i2] = pk(h0, h1);
        g_W2l[i2] = pk(w0 - h0, w1 - h1);
    } else if (idx < 98304 + 16384 + 768) {
        int p = idx - 98304 - 16384;
        float b;
        if (p < 256)      b = (p & 1) ? bla[p >> 1] : bga[p >> 1];
        else if (p < 512) { int q = p - 256; b = (q & 1) ? blb[q >> 1] : bgb[q >> 1]; }
        else              b = bgo[p - 512];
        g_bcat[p] = b;
    }
}

// ---------------- kernel 1: LN + big GEMM (768 cols) + fused epilogues ----------------
// block = 128 rows, 512 threads / 16 warps: wm = wid>>2 (m 32-slice), wn = wid&3 (n 32-slice)
__global__ void __launch_bounds__(NTHR, 1)
k_mma1(const float* __restrict__ vals,
       const float* __restrict__ lng, const float* __restrict__ lnb) {
    extern __shared__ char sm[];
    char*  Ash   = sm;
    char*  Asl   = sm + SM1_ASL;
    float* sBp   = (float*)(sm + SM1_BP);
    float* sbias = (float*)(sm + SM1_BIAS);

    const int tid  = threadIdx.x;
    const int lane = tid & 31;
    const int wid  = tid >> 5;
    const int wm   = wid >> 2;
    const int wn   = wid & 3;
    const size_t row0 = (size_t)blockIdx.x * MT;

    for (int i = tid; i < KGRP * CCH; i += NTHR) sBp[i] = 0.0f;
    for (int i = tid; i < 768; i += NTHR) sbias[i] = g_bcat[i];

    // ---- LN phase: 8 rows per warp, split hi/lo into smem A image ----
    {
        float4 g0 = *(const float4*)(lng + lane * 4);
        float4 g1 = *(const float4*)(lng + 128 + lane * 4);
        float4 b0 = *(const float4*)(lnb + lane * 4);
        float4 b1 = *(const float4*)(lnb + 128 + lane * 4);
        for (int rr = 0; rr < 8; ++rr) {
            int r = wid * 8 + rr;
            const float* vr = vals + (row0 + r) * CIN;
            float4 v0 = *(const float4*)(vr + lane * 4);
            float4 v1 = *(const float4*)(vr + 128 + lane * 4);
            float s = v0.x + v0.y + v0.z + v0.w + v1.x + v1.y + v1.z + v1.w;
            float q = v0.x*v0.x + v0.y*v0.y + v0.z*v0.z + v0.w*v0.w
                    + v1.x*v1.x + v1.y*v1.y + v1.z*v1.z + v1.w*v1.w;
            #pragma unroll
            for (int o = 16; o; o >>= 1) {
                s += __shfl_xor_sync(0xffffffffu, s, o);
                q += __shfl_xor_sync(0xffffffffu, q, o);
            }
            float mu  = s * (1.0f / 256.0f);
            float var = fmaxf(q * (1.0f / 256.0f) - mu * mu, 0.0f);
            float rs  = rsqrtf(var + 1e-5f);
            float x[8], h[8];
            x[0]=(v0.x-mu)*rs*g0.x+b0.x; x[1]=(v0.y-mu)*rs*g0.y+b0.y;
            x[2]=(v0.z-mu)*rs*g0.z+b0.z; x[3]=(v0.w-mu)*rs*g0.w+b0.w;
            x[4]=(v1.x-mu)*rs*g1.x+b1.x; x[5]=(v1.y-mu)*rs*g1.y+b1.y;
            x[6]=(v1.z-mu)*rs*g1.z+b1.z; x[7]=(v1.w-mu)*rs*g1.w+b1.w;
            #pragma unroll
            for (int e = 0; e < 8; ++e) h[e] = bfh(x[e]);
            *(uint2*)(Ash + r*AS1 + lane*8)       = make_uint2(pk(h[0],h[1]), pk(h[2],h[3]));
            *(uint2*)(Ash + r*AS1 + 256 + lane*8) = make_uint2(pk(h[4],h[5]), pk(h[6],h[7]));
            *(uint2*)(Asl + r*AS1 + lane*8)       = make_uint2(pk(x[0]-h[0],x[1]-h[1]), pk(x[2]-h[2],x[3]-h[3]));
            *(uint2*)(Asl + r*AS1 + 256 + lane*8) = make_uint2(pk(x[4]-h[4],x[5]-h[5]), pk(x[6]-h[6],x[7]-h[7]));
        }
    }
    __syncthreads();

    const uint32_t ash = smem_u32(Ash);
    const uint32_t asl = smem_u32(Asl);
    const int lrow = (lane & 7) + ((lane >> 3) & 1) * 8;
    const int lkof = ((lane >> 4) & 1) * 16;
    const uint32_t abase = (uint32_t)((wm * 32 + lrow) * AS1 + lkof);
    const int cls0 = (int)(row0 % KGRP);

    #pragma unroll 1
    for (int nt = 0; nt < 6; ++nt) {
        float acc[2][4][4];
        #pragma unroll
        for (int mb = 0; mb < 2; ++mb)
            #pragma unroll
            for (int nb = 0; nb < 4; ++nb)
                #pragma unroll
                for (int e = 0; e < 4; ++e) acc[mb][nb][e] = 0.0f;

        const uint2* __restrict__ BH = ((const uint2*)g_Wfh) + ((size_t)(nt*16)*16 + wn*4)*32 + lane;
        const uint2* __restrict__ BL = ((const uint2*)g_Wfl) + ((size_t)(nt*16)*16 + wn*4)*32 + lane;

        uint2 bh[2][4], bl[2][4];
        #pragma unroll
        for (int nb = 0; nb < 4; ++nb) {
            bh[0][nb] = BH[nb * 32];
            bl[0][nb] = BL[nb * 32];
        }
        #pragma unroll
        for (int kb = 0; kb < 16; ++kb) {
            const int cur = kb & 1, nxt = cur ^ 1;
            if (kb < 15) {
                #pragma unroll
                for (int nb = 0; nb < 4; ++nb) {
                    bh[nxt][nb] = BH[((kb + 1) * 16 + nb) * 32];
                    bl[nxt][nb] = BL[((kb + 1) * 16 + nb) * 32];
                }
            }
            uint32_t ah[2][4], al[2][4];
            #pragma unroll
            for (int mb = 0; mb < 2; ++mb) {
                uint32_t off = abase + mb * 16 * AS1 + kb * 32;
                ldm_x4(ah[mb], ash + off);
                ldm_x4(al[mb], asl + off);
            }
            #pragma unroll
            for (int nb = 0; nb < 4; ++nb) {
                #pragma unroll
                for (int mb = 0; mb < 2; ++mb) {
                    mma_bf16(acc[mb][nb], ah[mb], bh[cur][nb].x, bh[cur][nb].y);
                    mma_bf16(acc[mb][nb], ah[mb], bl[cur][nb].x, bl[cur][nb].y);
                    mma_bf16(acc[mb][nb], al[mb], bh[cur][nb].x, bh[cur][nb].y);
                }
            }
        }

        // ---- fused epilogue for this 128-col tile ----
        #pragma unroll
        for (int mb = 0; mb < 2; ++mb) {
            #pragma unroll
            for (int nb = 0; nb < 4; ++nb) {
                int cloc = (wn * 4 + nb) * 8 + (lane & 3) * 2;
                float bx = sbias[nt * 128 + cloc];
                float by = sbias[nt * 128 + cloc + 1];
                int lr0 = wm * 32 + mb * 16 + (lane >> 2);
                size_t r0 = row0 + lr0, r1 = r0 + 8;
                float y0 = acc[mb][nb][0] + bx;
                float y1 = acc[mb][nb][1] + by;
                float y2 = acc[mb][nb][2] + bx;
                float y3 = acc[mb][nb][3] + by;
                if (nt < 2) {
                    int ch = nt * 64 + (cloc >> 1);
                    g_a[r0 * CCH + ch] = sigf(y0) * y1;
                    g_a[r1 * CCH + ch] = sigf(y2) * y3;
                } else if (nt < 4) {
                    int ch = (nt - 2) * 64 + (cloc >> 1);
                    int c0 = (cls0 + lr0) % KGRP;
                    int c1 = (cls0 + lr0 + 8) % KGRP;
                    atomicAdd(&sBp[c0 * CCH + ch], sigf(y0) * y1);
                    atomicAdd(&sBp[c1 * CCH + ch], sigf(y2) * y3);
                } else {
                    int cg = (nt - 4) * 128 + cloc;
                    *(float2*)(g_gate + r0 * CIN + cg) = make_float2(sigf(y0), sigf(y1));
                    *(float2*)(g_gate + r1 * CIN + cg) = make_float2(sigf(y2), sigf(y3));
                }
            }
        }
    }
    __syncthreads();
    for (int i = tid; i < KGRP * CCH; i += NTHR)
        g_Bpart[(size_t)blockIdx.x * (KGRP * CCH) + i] = sBp[i];
}

// ---------------- reduce B partials: 2-stage, deterministic ----------------
__global__ void k_redB1() {          // grid (6, 25)
    int d = blockIdx.x * 256 + threadIdx.x;
    int b0 = blockIdx.y * 75;
    float s = 0.0f;
    for (int b = b0; b < b0 + 75; ++b) s += g_Bpart[(size_t)b * (KGRP * CCH) + d];
    g_B2[blockIdx.y * (KGRP * CCH) + d] = s;
}
__global__ void k_redB2() {          // grid 6
    int d = blockIdx.x * 256 + threadIdx.x;
    float s = 0.0f;
    for (int y = 0; y < 25; ++y) s += g_B2[y * (KGRP * CCH) + d];
    g_B[d] = s;
}

// ---------------- kernel 2: tri + LN + out GEMM (256 cols) + gate ----------------
__global__ void __launch_bounds__(NTHR, 1)
k_mma2(const float* __restrict__ lnog, const float* __restrict__ lnob,
       const float* __restrict__ blo, float* __restrict__ out) {
    extern __shared__ char sm[];
    char*  Ash = sm;
    char*  Asl = sm + SM2_ASL;
    float* Bsm = (float*)(sm + SM2_B);

    const int tid  = threadIdx.x;
    const int lane = tid & 31;
    const int wid  = tid >> 5;
    const int wm   = wid >> 2;
    const int wn   = wid & 3;
    const size_t row0 = (size_t)blockIdx.x * MT;

    for (int i = tid; i < KGRP * CCH; i += NTHR) Bsm[i] = g_B[i];
    __syncthreads();

    // ---- tri = a * B[row%12], LN over 128, split hi/lo into smem ----
    {
        float4 g4 = *(const float4*)(lnog + lane * 4);
        float4 b4 = *(const float4*)(lnob + lane * 4);
        for (int rr = 0; rr < 8; ++rr) {
            int r = wid * 8 + rr;
            size_t gr = row0 + r;
            float4 av = *(const float4*)(g_a + gr * CCH + lane * 4);
            const float* Br = Bsm + (int)(gr % KGRP) * CCH;
            float4 bv = *(const float4*)(Br + lane * 4);
            float t0 = av.x*bv.x, t1 = av.y*bv.y, t2 = av.z*bv.z, t3 = av.w*bv.w;
            float s = t0 + t1 + t2 + t3;
            float q = t0*t0 + t1*t1 + t2*t2 + t3*t3;
            #pragma unroll
            for (int o = 16; o; o >>= 1) {
                s += __shfl_xor_sync(0xffffffffu, s, o);
                q += __shfl_xor_sync(0xffffffffu, q, o);
            }
            float mu  = s * (1.0f / 128.0f);
            float var = fmaxf(q * (1.0f / 128.0f) - mu * mu, 0.0f);
            float rs  = rsqrtf(var + 1e-5f);
            float x0 = (t0 - mu) * rs * g4.x + b4.x;
            float x1 = (t1 - mu) * rs * g4.y + b4.y;
            float x2 = (t2 - mu) * rs * g4.z + b4.z;
            float x3 = (t3 - mu) * rs * g4.w + b4.w;
            float h0 = bfh(x0), h1 = bfh(x1), h2 = bfh(x2), h3 = bfh(x3);
            *(uint2*)(Ash + r*AS2 + lane*8) = make_uint2(pk(h0,h1), pk(h2,h3));
            *(uint2*)(Asl + r*AS2 + lane*8) = make_uint2(pk(x0-h0,x1-h1), pk(x2-h2,x3-h3));
        }
    }
    __syncthreads();

    const uint32_t ash = smem_u32(Ash);
    const uint32_t asl = smem_u32(Asl);
    const int lrow = (lane & 7) + ((lane >> 3) & 1) * 8;
    const int lkof = ((lane >> 4) & 1) * 16;
    const uint32_t abase = (uint32_t)((wm * 32 + lrow) * AS2 + lkof);

    #pragma unroll 1
    for (int nt = 0; nt < 2; ++nt) {
        float acc[2][4][4];
        #pragma unroll
        for (int mb = 0; mb < 2; ++mb)
            #pragma unroll
            for (int nb = 0; nb < 4; ++nb)
                #pragma unroll
                for (int e = 0; e < 4; ++e) acc[mb][nb][e] = 0.0f;

        const uint2* __restrict__ BH = ((const uint2*)g_W2h) + ((size_t)(nt*8)*16 + wn*4)*32 + lane;
        const uint2* __restrict__ BL = ((const uint2*)g_W2l) + ((size_t)(nt*8)*16 + wn*4)*32 + lane;

        uint2 bh[2][4], bl[2][4];
        #pragma unroll
        for (int nb = 0; nb < 4; ++nb) {
            bh[0][nb] = BH[nb * 32];
            bl[0][nb] = BL[nb * 32];
        }
        #pragma unroll
        for (int kb = 0; kb < 8; ++kb) {
            const int cur = kb & 1, nxt = cur ^ 1;
            if (kb < 7) {
                #pragma unroll
                for (int nb = 0; nb < 4; ++nb) {
                    bh[nxt][nb] = BH[((kb + 1) * 16 + nb) * 32];
                    bl[nxt][nb] = BL[((kb + 1) * 16 + nb) * 32];
                }
            }
            uint32_t ah[2][4], al[2][4];
            #pragma unroll
            for (int mb = 0; mb < 2; ++mb) {
                uint32_t off = abase + mb * 16 * AS2 + kb * 32;
                ldm_x4(ah[mb], ash + off);
                ldm_x4(al[mb], asl + off);
            }
            #pragma unroll
            for (int nb = 0; nb < 4; ++nb) {
                #pragma unroll
                for (int mb = 0; mb < 2; ++mb) {
                    mma_bf16(acc[mb][nb], ah[mb], bh[cur][nb].x, bh[cur][nb].y);
                    mma_bf16(acc[mb][nb], ah[mb], bl[cur][nb].x, bl[cur][nb].y);
                    mma_bf16(acc[mb][nb], al[mb], bh[cur][nb].x, bh[cur][nb].y);
                }
            }
        }

        // ---- epilogue: out = gate * (acc + blo) ----
        #pragma unroll
        for (int mb = 0; mb < 2; ++mb) {
            #pragma unroll
            for (int nb = 0; nb < 4; ++nb) {
                int c = nt * 128 + (wn * 4 + nb) * 8 + (lane & 3) * 2;
                float2 bias = *(const float2*)(blo + c);
                size_t r0 = row0 + wm * 32 + mb * 16 + (lane >> 2), r1 = r0 + 8;
                float2 gt0 = *(const float2*)(g_gate + r0 * CIN + c);
                float2 gt1 = *(const float2*)(g_gate + r1 * CIN + c);
                *(float2*)(out + r0 * CIN + c) =
                    make_float2(gt0.x * (acc[mb][nb][0] + bias.x),
                                gt0.y * (acc[mb][nb][1] + bias.y));
                *(float2*)(out + r1 * CIN + c) =
                    make_float2(gt1.x * (acc[mb][nb][2] + bias.x),
                                gt1.y * (acc[mb][nb][3] + bias.y));
            }
        }
    }
}

// ---------------- launch ----------------
extern "C" void kernel_launch(void* const* d_in, const int* in_sizes, int n_in,
                              void* d_out, int out_size) {
    const float* values  = (const float*)d_in[0];
    const float* ln_in_g = (const float*)d_in[1];
    const float* ln_in_b = (const float*)d_in[2];
    const float* W_ga    = (const float*)d_in[3];
    const float* b_ga    = (const float*)d_in[4];
    const float* W_la    = (const float*)d_in[5];
    const float* b_la    = (const float*)d_in[6];
    const float* W_gb    = (const float*)d_in[7];
    const float* b_gb    = (const float*)d_in[8];
    const float* W_lb    = (const float*)d_in[9];
    const float* b_lb    = (const float*)d_in[10];
    const float* ln_o_g  = (const float*)d_in[11];
    const float* ln_o_b  = (const float*)d_in[12];
    const float* W_go    = (const float*)d_in[13];
    const float* b_go    = (const float*)d_in[14];
    const float* W_lo    = (const float*)d_in[15];
    const float* b_lo    = (const float*)d_in[16];
    float* out = (float*)d_out;

    cudaFuncSetAttribute(k_mma1, cudaFuncAttributeMaxDynamicSharedMemorySize, SM1_TOTAL);
    cudaFuncSetAttribute(k_mma2, cudaFuncAttributeMaxDynamicSharedMemorySize, SM2_TOTAL);

    int pack_threads = 98304 + 16384 + 768;
    k_pack<<<(pack_threads + 255) / 256, 256>>>(W_ga, b_ga, W_la, b_la,
                                                W_gb, b_gb, W_lb, b_lb,
                                                W_go, b_go, W_lo);
    k_mma1<<<NRB1, NTHR, SM1_TOTAL>>>(values, ln_in_g, ln_in_b);
    k_redB1<<<dim3(6, 25), 256>>>();
    k_redB2<<<6, 256>>>();
    k_mma2<<<NRB1, NTHR, SM2_TOTAL>>>(ln_o_g, ln_o_b, b_lo, out);
}

// round 7
// speedup vs baseline: 3.1606x; 1.0078x over previous
#include <cuda_runtime.h>
#include <cuda_bf16.h>
#include <math.h>
#include <stdint.h>

// ---------------- problem constants ----------------
#define NNZ   240000
#define CIN   256
#define CCH   128
#define KGRP  12
#define MT    128
#define NRB1  (NNZ / MT)          // 1875
#define NTHR  512

#define AS1   528                 // A smem row stride bytes (K=256 bf16 + 16B pad)
#define AS2   272                 // K=128 bf16 + 16B pad

// smem layout k_mma1 (bytes)
#define SM1_ASL   (128 * AS1)
#define SM1_BP    (2 * 128 * AS1)
#define SM1_BIAS  (SM1_BP + KGRP * CCH * 4)
#define SM1_TOTAL (SM1_BIAS + 768 * 4)      // 144384
// smem layout k_mma2
#define SM2_ASL   (128 * AS2)
#define SM2_B     (2 * 128 * AS2)
#define SM2_TOTAL (SM2_B + KGRP * CCH * 4)  // 75776

// ---------------- device scratch ----------------
__device__ __align__(16) uint32_t g_Wfh[6 * 16 * 16 * 64];   // big-GEMM B frags hi
__device__ __align__(16) uint32_t g_Wfl[6 * 16 * 16 * 64];
__device__ __align__(16) uint32_t g_W2h[2 * 8 * 16 * 64];    // out-GEMM B frags hi
__device__ __align__(16) uint32_t g_W2l[2 * 8 * 16 * 64];
__device__ float g_bcat[768];                                // pair-interleaved bias
__device__ float g_a[(size_t)NNZ * CCH];
__device__ float g_gate[(size_t)NNZ * CIN];
__device__ float g_Bpart[(size_t)NRB1 * KGRP * CCH];
__device__ float g_B2[25 * KGRP * CCH];
__device__ float g_B[KGRP * CCH];

__device__ __forceinline__ float sigf(float x) { return 1.0f / (1.0f + expf(-x)); }

__device__ __forceinline__ uint32_t smem_u32(const void* p) {
    uint32_t a;
    asm("{ .reg .u64 t; cvta.to.shared.u64 t, %1; cvt.u32.u64 %0, t; }" : "=r"(a) : "l"(p));
    return a;
}
__device__ __forceinline__ void ldm_x4(uint32_t* r, uint32_t addr) {
    asm volatile("ldmatrix.sync.aligned.m8n8.x4.shared.b16 {%0,%1,%2,%3}, [%4];"
        : "=r"(r[0]), "=r"(r[1]), "=r"(r[2]), "=r"(r[3]) : "r"(addr));
}
__device__ __forceinline__ void mma_bf16(float* d, const uint32_t* a, uint32_t b0, uint32_t b1) {
    asm volatile("mma.sync.aligned.m16n8k16.row.col.f32.bf16.bf16.f32 "
        "{%0,%1,%2,%3}, {%4,%5,%6,%7}, {%8,%9}, {%0,%1,%2,%3};"
        : "+f"(d[0]), "+f"(d[1]), "+f"(d[2]), "+f"(d[3])
        : "r"(a[0]), "r"(a[1]), "r"(a[2]), "r"(a[3]), "r"(b0), "r"(b1));
}
__device__ __forceinline__ uint32_t pk(float a, float b) {
    return (uint32_t)__bfloat16_as_ushort(__float2bfloat16(a))
         | ((uint32_t)__bfloat16_as_ushort(__float2bfloat16(b)) << 16);
}
__device__ __forceinline__ float bfh(float x) {
    return __bfloat162float(__float2bfloat16(x));
}

// ---------------- kernel: pack weights into fragment-ordered hi/lo ----------------
// packed col p: [0,256)=pair-interleave ga/la (even=gate), [256,512)=gb/lb, [512,768)=go
// frag idx = ((nt*16+kb)*16+nb)*64 + lane*2 + reg
__global__ void k_pack(const float* __restrict__ Wga, const float* __restrict__ bga,
                       const float* __restrict__ Wla, const float* __restrict__ bla,
                       const float* __restrict__ Wgb, const float* __restrict__ bgb,
                       const float* __restrict__ Wlb, const float* __restrict__ blb,
                       const float* __restrict__ Wgo, const float* __restrict__ bgo,
                       const float* __restrict__ Wlo) {
    int idx = blockIdx.x * blockDim.x + threadIdx.x;
    if (idx < 98304) {
        int lane2 = idx & 63, lane = lane2 >> 1, reg = lane2 & 1;
        int nb = (idx >> 6) & 15, kb = (idx >> 10) & 15, nt = idx >> 14;
        int k0 = kb * 16 + (lane & 3) * 2 + reg * 8;
        int p  = nt * 128 + nb * 8 + (lane >> 2);
        const float* W; int c;
        if (p < 256)      { c = p >> 1;                W = (p & 1) ? Wla : Wga; }
        else if (p < 512) { int q = p - 256; c = q >> 1; W = (q & 1) ? Wlb : Wgb; }
        else              { c = p - 512;               W = Wgo; }
        float w0 = W[c * CIN + k0], w1 = W[c * CIN + k0 + 1];
        float h0 = bfh(w0), h1 = bfh(w1);
        g_Wfh[idx] = pk(h0, h1);
        g_Wfl[idx] = pk(w0 - h0, w1 - h1);
    } else if (idx < 98304 + 16384) {
        int i2 = idx - 98304;
        int lane2 = i2 & 63, lane = lane2 >> 1, reg = lane2 & 1;
        int nb = (i2 >> 6) & 15, kb = (i2 >> 10) & 7, nt = i2 >> 13;
        int k0 = kb * 16 + (lane & 3) * 2 + reg * 8;
        int j  = nt * 128 + nb * 8 + (lane >> 2);
        float w0 = Wlo[j * CCH + k0], w1 = Wlo[j * CCH + k0 + 1];
        float h0 = bfh(w0), h1 = bfh(w1);
        g_W2h[i2] = pk(h0, h1);
        g_W2l[i2] = pk(w0 - h0, w1 - h1);
    } else if (idx < 98304 + 16384 + 768) {
        int p = idx - 98304 - 16384;
        float b;
        if (p < 256)      b = (p & 1) ? bla[p >> 1] : bga[p >> 1];
        else if (p < 512) { int q = p - 256; b = (q & 1) ? blb[q >> 1] : bgb[q >> 1]; }
        else              b = bgo[p - 512];
        g_bcat[p] = b;
    }
}

// ---------------- kernel 1: LN + big GEMM (768 cols) + fused epilogues ----------------
// block = 128 rows, 512 threads / 16 warps: wm = wid>>3 (m 64-slice), wn = wid&7 (n 16-slice)
__global__ void __launch_bounds__(NTHR, 1)
k_mma1(const float* __restrict__ vals,
       const float* __restrict__ lng, const float* __restrict__ lnb) {
    extern __shared__ char sm[];
    char*  Ash   = sm;
    char*  Asl   = sm + SM1_ASL;
    float* sBp   = (float*)(sm + SM1_BP);
    float* sbias = (float*)(sm + SM1_BIAS);

    const int tid  = threadIdx.x;
    const int lane = tid & 31;
    const int wid  = tid >> 5;
    const int wm   = wid >> 3;    // 0..1
    const int wn   = wid & 7;     // 0..7
    const size_t row0 = (size_t)blockIdx.x * MT;

    for (int i = tid; i < KGRP * CCH; i += NTHR) sBp[i] = 0.0f;
    for (int i = tid; i < 768; i += NTHR) sbias[i] = g_bcat[i];

    // ---- LN phase: 8 rows per warp, split hi/lo into smem A image ----
    {
        float4 g0 = *(const float4*)(lng + lane * 4);
        float4 g1 = *(const float4*)(lng + 128 + lane * 4);
        float4 b0 = *(const float4*)(lnb + lane * 4);
        float4 b1 = *(const float4*)(lnb + 128 + lane * 4);
        for (int rr = 0; rr < 8; ++rr) {
            int r = wid * 8 + rr;
            const float* vr = vals + (row0 + r) * CIN;
            float4 v0 = *(const float4*)(vr + lane * 4);
            float4 v1 = *(const float4*)(vr + 128 + lane * 4);
            float s = v0.x + v0.y + v0.z + v0.w + v1.x + v1.y + v1.z + v1.w;
            float q = v0.x*v0.x + v0.y*v0.y + v0.z*v0.z + v0.w*v0.w
                    + v1.x*v1.x + v1.y*v1.y + v1.z*v1.z + v1.w*v1.w;
            #pragma unroll
            for (int o = 16; o; o >>= 1) {
                s += __shfl_xor_sync(0xffffffffu, s, o);
                q += __shfl_xor_sync(0xffffffffu, q, o);
            }
            float mu  = s * (1.0f / 256.0f);
            float var = fmaxf(q * (1.0f / 256.0f) - mu * mu, 0.0f);
            float rs  = rsqrtf(var + 1e-5f);
            float x[8], h[8];
            x[0]=(v0.x-mu)*rs*g0.x+b0.x; x[1]=(v0.y-mu)*rs*g0.y+b0.y;
            x[2]=(v0.z-mu)*rs*g0.z+b0.z; x[3]=(v0.w-mu)*rs*g0.w+b0.w;
            x[4]=(v1.x-mu)*rs*g1.x+b1.x; x[5]=(v1.y-mu)*rs*g1.y+b1.y;
            x[6]=(v1.z-mu)*rs*g1.z+b1.z; x[7]=(v1.w-mu)*rs*g1.w+b1.w;
            #pragma unroll
            for (int e = 0; e < 8; ++e) h[e] = bfh(x[e]);
            *(uint2*)(Ash + r*AS1 + lane*8)       = make_uint2(pk(h[0],h[1]), pk(h[2],h[3]));
            *(uint2*)(Ash + r*AS1 + 256 + lane*8) = make_uint2(pk(h[4],h[5]), pk(h[6],h[7]));
            *(uint2*)(Asl + r*AS1 + lane*8)       = make_uint2(pk(x[0]-h[0],x[1]-h[1]), pk(x[2]-h[2],x[3]-h[3]));
            *(uint2*)(Asl + r*AS1 + 256 + lane*8) = make_uint2(pk(x[4]-h[4],x[5]-h[5]), pk(x[6]-h[6],x[7]-h[7]));
        }
    }
    __syncthreads();

    const uint32_t ash = smem_u32(Ash);
    const uint32_t asl = smem_u32(Asl);
    const int lrow = (lane & 7) + ((lane >> 3) & 1) * 8;
    const int lkof = ((lane >> 4) & 1) * 16;
    const uint32_t abase = (uint32_t)((wm * 64 + lrow) * AS1 + lkof);
    const int cls0 = (int)(row0 % KGRP);

    #pragma unroll 1
    for (int nt = 0; nt < 6; ++nt) {
        float acc[4][2][4];
        #pragma unroll
        for (int mb = 0; mb < 4; ++mb)
            #pragma unroll
            for (int nb = 0; nb < 2; ++nb)
                #pragma unroll
                for (int e = 0; e < 4; ++e) acc[mb][nb][e] = 0.0f;

        const uint2* __restrict__ BH = ((const uint2*)g_Wfh) + ((size_t)(nt*16)*16 + wn*2)*32 + lane;
        const uint2* __restrict__ BL = ((const uint2*)g_Wfl) + ((size_t)(nt*16)*16 + wn*2)*32 + lane;

        // 3-deep register pipeline on B (prefetch distance 2)
        uint2 bh[3][2], bl[3][2];
        #pragma unroll
        for (int pf = 0; pf < 2; ++pf)
            #pragma unroll
            for (int nb = 0; nb < 2; ++nb) {
                bh[pf][nb] = BH[(pf * 16 + nb) * 32];
                bl[pf][nb] = BL[(pf * 16 + nb) * 32];
            }
        #pragma unroll
        for (int kb = 0; kb < 16; ++kb) {
            const int cur = kb % 3;
            if (kb < 14) {
                const int dst = (kb + 2) % 3;
                #pragma unroll
                for (int nb = 0; nb < 2; ++nb) {
                    bh[dst][nb] = BH[((kb + 2) * 16 + nb) * 32];
                    bl[dst][nb] = BL[((kb + 2) * 16 + nb) * 32];
                }
            }
            #pragma unroll
            for (int mb = 0; mb < 4; ++mb) {
                uint32_t ah[4], al[4];
                uint32_t off = abase + mb * 16 * AS1 + kb * 32;
                ldm_x4(ah, ash + off);
                ldm_x4(al, asl + off);
                #pragma unroll
                for (int nb = 0; nb < 2; ++nb) {
                    mma_bf16(acc[mb][nb], ah, bh[cur][nb].x, bh[cur][nb].y);
                    mma_bf16(acc[mb][nb], ah, bl[cur][nb].x, bl[cur][nb].y);
                    mma_bf16(acc[mb][nb], al, bh[cur][nb].x, bh[cur][nb].y);
                }
            }
        }

        // ---- fused epilogue for this 128-col tile ----
        #pragma unroll
        for (int mb = 0; mb < 4; ++mb) {
            #pragma unroll
            for (int nb = 0; nb < 2; ++nb) {
                int cloc = (wn * 2 + nb) * 8 + (lane & 3) * 2;
                float bx = sbias[nt * 128 + cloc];
                float by = sbias[nt * 128 + cloc + 1];
                int lr0 = wm * 64 + mb * 16 + (lane >> 2);
                size_t r0 = row0 + lr0, r1 = r0 + 8;
                float y0 = acc[mb][nb][0] + bx;
                float y1 = acc[mb][nb][1] + by;
                float y2 = acc[mb][nb][2] + bx;
                float y3 = acc[mb][nb][3] + by;
                if (nt < 2) {
                    int ch = nt * 64 + (cloc >> 1);
                    g_a[r0 * CCH + ch] = sigf(y0) * y1;
                    g_a[r1 * CCH + ch] = sigf(y2) * y3;
                } else if (nt < 4) {
                    int ch = (nt - 2) * 64 + (cloc >> 1);
                    int c0 = (cls0 + lr0) % KGRP;
                    int c1 = (cls0 + lr0 + 8) % KGRP;
                    atomicAdd(&sBp[c0 * CCH + ch], sigf(y0) * y1);
                    atomicAdd(&sBp[c1 * CCH + ch], sigf(y2) * y3);
                } else {
                    int cg = (nt - 4) * 128 + cloc;
                    *(float2*)(g_gate + r0 * CIN + cg) = make_float2(sigf(y0), sigf(y1));
                    *(float2*)(g_gate + r1 * CIN + cg) = make_float2(sigf(y2), sigf(y3));
                }
            }
        }
    }
    __syncthreads();
    for (int i = tid; i < KGRP * CCH; i += NTHR)
        g_Bpart[(size_t)blockIdx.x * (KGRP * CCH) + i] = sBp[i];
}

// ---------------- reduce B partials: 2-stage, deterministic ----------------
__global__ void k_redB1() {          // grid (6, 25)
    int d = blockIdx.x * 256 + threadIdx.x;
    int b0 = blockIdx.y * 75;
    float s = 0.0f;
    for (int b = b0; b < b0 + 75; ++b) s += g_Bpart[(size_t)b * (KGRP * CCH) + d];
    g_B2[blockIdx.y * (KGRP * CCH) + d] = s;
}
__global__ void k_redB2() {          // grid 6
    int d = blockIdx.x * 256 + threadIdx.x;
    float s = 0.0f;
    for (int y = 0; y < 25; ++y) s += g_B2[y * (KGRP * CCH) + d];
    g_B[d] = s;
}

// ---------------- kernel 2: tri + LN + out GEMM (256 cols) + gate ----------------
__global__ void __launch_bounds__(NTHR, 1)
k_mma2(const float* __restrict__ lnog, const float* __restrict__ lnob,
       const float* __restrict__ blo, float* __restrict__ out) {
    extern __shared__ char sm[];
    char*  Ash = sm;
    char*  Asl = sm + SM2_ASL;
    float* Bsm = (float*)(sm + SM2_B);

    const int tid  = threadIdx.x;
    const int lane = tid & 31;
    const int wid  = tid >> 5;
    const int wm   = wid >> 3;    // 0..1
    const int wn   = wid & 7;     // 0..7
    const size_t row0 = (size_t)blockIdx.x * MT;

    for (int i = tid; i < KGRP * CCH; i += NTHR) Bsm[i] = g_B[i];
    __syncthreads();

    // ---- tri = a * B[row%12], LN over 128, split hi/lo into smem ----
    {
        float4 g4 = *(const float4*)(lnog + lane * 4);
        float4 b4 = *(const float4*)(lnob + lane * 4);
        for (int rr = 0; rr < 8; ++rr) {
            int r = wid * 8 + rr;
            size_t gr = row0 + r;
            float4 av = *(const float4*)(g_a + gr * CCH + lane * 4);
            const float* Br = Bsm + (int)(gr % KGRP) * CCH;
            float4 bv = *(const float4*)(Br + lane * 4);
            float t0 = av.x*bv.x, t1 = av.y*bv.y, t2 = av.z*bv.z, t3 = av.w*bv.w;
            float s = t0 + t1 + t2 + t3;
            float q = t0*t0 + t1*t1 + t2*t2 + t3*t3;
            #pragma unroll
            for (int o = 16; o; o >>= 1) {
                s += __shfl_xor_sync(0xffffffffu, s, o);
                q += __shfl_xor_sync(0xffffffffu, q, o);
            }
            float mu  = s * (1.0f / 128.0f);
            float var = fmaxf(q * (1.0f / 128.0f) - mu * mu, 0.0f);
            float rs  = rsqrtf(var + 1e-5f);
            float x0 = (t0 - mu) * rs * g4.x + b4.x;
            float x1 = (t1 - mu) * rs * g4.y + b4.y;
            float x2 = (t2 - mu) * rs * g4.z + b4.z;
            float x3 = (t3 - mu) * rs * g4.w + b4.w;
            float h0 = bfh(x0), h1 = bfh(x1), h2 = bfh(x2), h3 = bfh(x3);
            *(uint2*)(Ash + r*AS2 + lane*8) = make_uint2(pk(h0,h1), pk(h2,h3));
            *(uint2*)(Asl + r*AS2 + lane*8) = make_uint2(pk(x0-h0,x1-h1), pk(x2-h2,x3-h3));
        }
    }
    __syncthreads();

    const uint32_t ash = smem_u32(Ash);
    const uint32_t asl = smem_u32(Asl);
    const int lrow = (lane & 7) + ((lane >> 3) & 1) * 8;
    const int lkof = ((lane >> 4) & 1) * 16;
    const uint32_t abase = (uint32_t)((wm * 64 + lrow) * AS2 + lkof);

    #pragma unroll 1
    for (int nt = 0; nt < 2; ++nt) {
        float acc[4][2][4];
        #pragma unroll
        for (int mb = 0; mb < 4; ++mb)
            #pragma unroll
            for (int nb = 0; nb < 2; ++nb)
                #pragma unroll
                for (int e = 0; e < 4; ++e) acc[mb][nb][e] = 0.0f;

        const uint2* __restrict__ BH = ((const uint2*)g_W2h) + ((size_t)(nt*8)*16 + wn*2)*32 + lane;
        const uint2* __restrict__ BL = ((const uint2*)g_W2l) + ((size_t)(nt*8)*16 + wn*2)*32 + lane;

        uint2 bh[3][2], bl[3][2];
        #pragma unroll
        for (int pf = 0; pf < 2; ++pf)
            #pragma unroll
            for (int nb = 0; nb < 2; ++nb) {
                bh[pf][nb] = BH[(pf * 16 + nb) * 32];
                bl[pf][nb] = BL[(pf * 16 + nb) * 32];
            }
        #pragma unroll
        for (int kb = 0; kb < 8; ++kb) {
            const int cur = kb % 3;
            if (kb < 6) {
                const int dst = (kb + 2) % 3;
                #pragma unroll
                for (int nb = 0; nb < 2; ++nb) {
                    bh[dst][nb] = BH[((kb + 2) * 16 + nb) * 32];
                    bl[dst][nb] = BL[((kb + 2) * 16 + nb) * 32];
                }
            }
            #pragma unroll
            for (int mb = 0; mb < 4; ++mb) {
                uint32_t ah[4], al[4];
                uint32_t off = abase + mb * 16 * AS2 + kb * 32;
                ldm_x4(ah, ash + off);
                ldm_x4(al, asl + off);
                #pragma unroll
                for (int nb = 0; nb < 2; ++nb) {
                    mma_bf16(acc[mb][nb], ah, bh[cur][nb].x, bh[cur][nb].y);
                    mma_bf16(acc[mb][nb], ah, bl[cur][nb].x, bl[cur][nb].y);
                    mma_bf16(acc[mb][nb], al, bh[cur][nb].x, bh[cur][nb].y);
                }
            }
        }

        // ---- epilogue: out = gate * (acc + blo) ----
        #pragma unroll
        for (int mb = 0; mb < 4; ++mb) {
            #pragma unroll
            for (int nb = 0; nb < 2; ++nb) {
                int c = nt * 128 + (wn * 2 + nb) * 8 + (lane & 3) * 2;
                float2 bias = *(const float2*)(blo + c);
                size_t r0 = row0 + wm * 64 + mb * 16 + (lane >> 2), r1 = r0 + 8;
                float2 gt0 = *(const float2*)(g_gate + r0 * CIN + c);
                float2 gt1 = *(const float2*)(g_gate + r1 * CIN + c);
                *(float2*)(out + r0 * CIN + c) =
                    make_float2(gt0.x * (acc[mb][nb][0] + bias.x),
                                gt0.y * (acc[mb][nb][1] + bias.y));
                *(float2*)(out + r1 * CIN + c) =
                    make_float2(gt1.x * (acc[mb][nb][2] + bias.x),
                                gt1.y * (acc[mb][nb][3] + bias.y));
            }
        }
    }
}

// ---------------- launch ----------------
extern "C" void kernel_launch(void* const* d_in, const int* in_sizes, int n_in,
                              void* d_out, int out_size) {
    const float* values  = (const float*)d_in[0];
    const float* ln_in_g = (const float*)d_in[1];
    const float* ln_in_b = (const float*)d_in[2];
    const float* W_ga    = (const float*)d_in[3];
    const float* b_ga    = (const float*)d_in[4];
    const float* W_la    = (const float*)d_in[5];
    const float* b_la    = (const float*)d_in[6];
    const float* W_gb    = (const float*)d_in[7];
    const float* b_gb    = (const float*)d_in[8];
    const float* W_lb    = (const float*)d_in[9];
    const float* b_lb    = (const float*)d_in[10];
    const float* ln_o_g  = (const float*)d_in[11];
    const float* ln_o_b  = (const float*)d_in[12];
    const float* W_go    = (const float*)d_in[13];
    const float* b_go    = (const float*)d_in[14];
    const float* W_lo    = (const float*)d_in[15];
    const float* b_lo    = (const float*)d_in[16];
    float* out = (float*)d_out;

    cudaFuncSetAttribute(k_mma1, cudaFuncAttributeMaxDynamicSharedMemorySize, SM1_TOTAL);
    cudaFuncSetAttribute(k_mma2, cudaFuncAttributeMaxDynamicSharedMemorySize, SM2_TOTAL);

    int pack_threads = 98304 + 16384 + 768;
    k_pack<<<(pack_threads + 255) / 256, 256>>>(W_ga, b_ga, W_la, b_la,
                                                W_gb, b_gb, W_lb, b_lb,
                                                W_go, b_go, W_lo);
    k_mma1<<<NRB1, NTHR, SM1_TOTAL>>>(values, ln_in_g, ln_in_b);
    k_redB1<<<dim3(6, 25), 256>>>();
    k_redB2<<<6, 256>>>();
    k_mma2<<<NRB1, NTHR, SM2_TOTAL>>>(ln_o_g, ln_o_b, b_lo, out);
}

// round 8
// speedup vs baseline: 4.1858x; 1.3244x over previous
#include <cuda_runtime.h>
#include <cuda_fp16.h>
#include <math.h>
#include <stdint.h>

// ---------------- problem constants ----------------
#define NNZ   240000
#define CIN   256
#define CCH   128
#define KGRP  12
#define MT    128
#define NRB1  (NNZ / MT)          // 1875
#define NTHR  512

#define AS1   528                 // A smem row stride bytes (K=256 fp16 + 16B pad)
#define AS2   272                 // K=128 fp16 + 16B pad

// smem layout k_mma1 (bytes): single A image now (fp16 hi only)
#define SM1_BP    (128 * AS1)
#define SM1_BIAS  (SM1_BP + KGRP * CCH * 4)
#define SM1_TOTAL (SM1_BIAS + 768 * 4)      // 76800
// smem layout k_mma2
#define SM2_B     (128 * AS2)
#define SM2_TOTAL (SM2_B + KGRP * CCH * 4)  // 40960

// ---------------- device scratch ----------------
__device__ __align__(16) uint32_t g_Wfh[6 * 16 * 16 * 64];   // big-GEMM B frags hi (fp16)
__device__ __align__(16) uint32_t g_Wfl[6 * 16 * 16 * 64];   // lo residual (fp16)
__device__ __align__(16) uint32_t g_W2h[2 * 8 * 16 * 64];    // out-GEMM B frags hi
__device__ __align__(16) uint32_t g_W2l[2 * 8 * 16 * 64];
__device__ float g_bcat[768];                                // pair-interleaved bias
__device__ float g_a[(size_t)NNZ * CCH];
__device__ float g_gate[(size_t)NNZ * CIN];
__device__ float g_Bpart[(size_t)NRB1 * KGRP * CCH];
__device__ float g_B2[25 * KGRP * CCH];
__device__ float g_B[KGRP * CCH];

__device__ __forceinline__ float sigf(float x) { return 1.0f / (1.0f + expf(-x)); }

__device__ __forceinline__ uint32_t smem_u32(const void* p) {
    uint32_t a;
    asm("{ .reg .u64 t; cvta.to.shared.u64 t, %1; cvt.u32.u64 %0, t; }" : "=r"(a) : "l"(p));
    return a;
}
__device__ __forceinline__ void ldm_x4(uint32_t* r, uint32_t addr) {
    asm volatile("ldmatrix.sync.aligned.m8n8.x4.shared.b16 {%0,%1,%2,%3}, [%4];"
        : "=r"(r[0]), "=r"(r[1]), "=r"(r[2]), "=r"(r[3]) : "r"(addr));
}
__device__ __forceinline__ void mma_f16(float* d, const uint32_t* a, uint32_t b0, uint32_t b1) {
    asm volatile("mma.sync.aligned.m16n8k16.row.col.f32.f16.f16.f32 "
        "{%0,%1,%2,%3}, {%4,%5,%6,%7}, {%8,%9}, {%0,%1,%2,%3};"
        : "+f"(d[0]), "+f"(d[1]), "+f"(d[2]), "+f"(d[3])
        : "r"(a[0]), "r"(a[1]), "r"(a[2]), "r"(a[3]), "r"(b0), "r"(b1));
}
__device__ __forceinline__ uint32_t pk(float a, float b) {
    __half2 h = __floats2half2_rn(a, b);
    return *(uint32_t*)&h;
}
__device__ __forceinline__ float fph(float x) {    // fp16-rounded value
    return __half2float(__float2half_rn(x));
}

// ---------------- kernel: pack weights into fragment-ordered fp16 hi/lo ----------------
// packed col p: [0,256)=pair-interleave ga/la (even=gate), [256,512)=gb/lb, [512,768)=go
// frag idx = ((nt*16+kb)*16+nb)*64 + lane*2 + reg
__global__ void k_pack(const float* __restrict__ Wga, const float* __restrict__ bga,
                       const float* __restrict__ Wla, const float* __restrict__ bla,
                       const float* __restrict__ Wgb, const float* __restrict__ bgb,
                       const float* __restrict__ Wlb, const float* __restrict__ blb,
                       const float* __restrict__ Wgo, const float* __restrict__ bgo,
                       const float* __restrict__ Wlo) {
    int idx = blockIdx.x * blockDim.x + threadIdx.x;
    if (idx < 98304) {
        int lane2 = idx & 63, lane = lane2 >> 1, reg = lane2 & 1;
        int nb = (idx >> 6) & 15, kb = (idx >> 10) & 15, nt = idx >> 14;
        int k0 = kb * 16 + (lane & 3) * 2 + reg * 8;
        int p  = nt * 128 + nb * 8 + (lane >> 2);
        const float* W; int c;
        if (p < 256)      { c = p >> 1;                W = (p & 1) ? Wla : Wga; }
        else if (p < 512) { int q = p - 256; c = q >> 1; W = (q & 1) ? Wlb : Wgb; }
        else              { c = p - 512;               W = Wgo; }
        float w0 = W[c * CIN + k0], w1 = W[c * CIN + k0 + 1];
        float h0 = fph(w0), h1 = fph(w1);
        g_Wfh[idx] = pk(h0, h1);
        g_Wfl[idx] = pk(w0 - h0, w1 - h1);
    } else if (idx < 98304 + 16384) {
        int i2 = idx - 98304;
        int lane2 = i2 & 63, lane = lane2 >> 1, reg = lane2 & 1;
        int nb = (i2 >> 6) & 15, kb = (i2 >> 10) & 7, nt = i2 >> 13;
        int k0 = kb * 16 + (lane & 3) * 2 + reg * 8;
        int j  = nt * 128 + nb * 8 + (lane >> 2);
        float w0 = Wlo[j * CCH + k0], w1 = Wlo[j * CCH + k0 + 1];
        float h0 = fph(w0), h1 = fph(w1);
        g_W2h[i2] = pk(h0, h1);
        g_W2l[i2] = pk(w0 - h0, w1 - h1);
    } else if (idx < 98304 + 16384 + 768) {
        int p = idx - 98304 - 16384;
        float b;
        if (p < 256)      b = (p & 1) ? bla[p >> 1] : bga[p >> 1];
        else if (p < 512) { int q = p - 256; b = (q & 1) ? blb[q >> 1] : bgb[q >> 1]; }
        else              b = bgo[p - 512];
        g_bcat[p] = b;
    }
}

// ---------------- kernel 1: LN + big GEMM (768 cols) + fused epilogues ----------------
// block = 128 rows, 512 threads / 16 warps: wm = wid>>3 (m 64-slice), wn = wid&7 (n 16-slice)
__global__ void __launch_bounds__(NTHR, 1)
k_mma1(const float* __restrict__ vals,
       const float* __restrict__ lng, const float* __restrict__ lnb) {
    extern __shared__ char sm[];
    char*  Ash   = sm;
    float* sBp   = (float*)(sm + SM1_BP);
    float* sbias = (float*)(sm + SM1_BIAS);

    const int tid  = threadIdx.x;
    const int lane = tid & 31;
    const int wid  = tid >> 5;
    const int wm   = wid >> 3;    // 0..1
    const int wn   = wid & 7;     // 0..7
    const size_t row0 = (size_t)blockIdx.x * MT;

    for (int i = tid; i < KGRP * CCH; i += NTHR) sBp[i] = 0.0f;
    for (int i = tid; i < 768; i += NTHR) sbias[i] = g_bcat[i];

    // ---- LN phase: 8 rows per warp, fp16 into smem A image ----
    {
        float4 g0 = *(const float4*)(lng + lane * 4);
        float4 g1 = *(const float4*)(lng + 128 + lane * 4);
        float4 b0 = *(const float4*)(lnb + lane * 4);
        float4 b1 = *(const float4*)(lnb + 128 + lane * 4);
        for (int rr = 0; rr < 8; ++rr) {
            int r = wid * 8 + rr;
            const float* vr = vals + (row0 + r) * CIN;
            float4 v0 = *(const float4*)(vr + lane * 4);
            float4 v1 = *(const float4*)(vr + 128 + lane * 4);
            float s = v0.x + v0.y + v0.z + v0.w + v1.x + v1.y + v1.z + v1.w;
            float q = v0.x*v0.x + v0.y*v0.y + v0.z*v0.z + v0.w*v0.w
                    + v1.x*v1.x + v1.y*v1.y + v1.z*v1.z + v1.w*v1.w;
            #pragma unroll
            for (int o = 16; o; o >>= 1) {
                s += __shfl_xor_sync(0xffffffffu, s, o);
                q += __shfl_xor_sync(0xffffffffu, q, o);
            }
            float mu  = s * (1.0f / 256.0f);
            float var = fmaxf(q * (1.0f / 256.0f) - mu * mu, 0.0f);
            float rs  = rsqrtf(var + 1e-5f);
            float x[8];
            x[0]=(v0.x-mu)*rs*g0.x+b0.x; x[1]=(v0.y-mu)*rs*g0.y+b0.y;
            x[2]=(v0.z-mu)*rs*g0.z+b0.z; x[3]=(v0.w-mu)*rs*g0.w+b0.w;
            x[4]=(v1.x-mu)*rs*g1.x+b1.x; x[5]=(v1.y-mu)*rs*g1.y+b1.y;
            x[6]=(v1.z-mu)*rs*g1.z+b1.z; x[7]=(v1.w-mu)*rs*g1.w+b1.w;
            *(uint2*)(Ash + r*AS1 + lane*8)       = make_uint2(pk(x[0],x[1]), pk(x[2],x[3]));
            *(uint2*)(Ash + r*AS1 + 256 + lane*8) = make_uint2(pk(x[4],x[5]), pk(x[6],x[7]));
        }
    }
    __syncthreads();

    const uint32_t ash = smem_u32(Ash);
    const int lrow = (lane & 7) + ((lane >> 3) & 1) * 8;
    const int lkof = ((lane >> 4) & 1) * 16;
    const uint32_t abase = (uint32_t)((wm * 64 + lrow) * AS1 + lkof);
    const int cls0 = (int)(row0 % KGRP);

    #pragma unroll 1
    for (int nt = 0; nt < 6; ++nt) {
        float acc[4][2][4];
        #pragma unroll
        for (int mb = 0; mb < 4; ++mb)
            #pragma unroll
            for (int nb = 0; nb < 2; ++nb)
                #pragma unroll
                for (int e = 0; e < 4; ++e) acc[mb][nb][e] = 0.0f;

        const uint2* __restrict__ BH = ((const uint2*)g_Wfh) + ((size_t)(nt*16)*16 + wn*2)*32 + lane;
        const uint2* __restrict__ BL = ((const uint2*)g_Wfl) + ((size_t)(nt*16)*16 + wn*2)*32 + lane;

        // 3-deep register pipeline on B (prefetch distance 2)
        uint2 bh[3][2], bl[3][2];
        #pragma unroll
        for (int pf = 0; pf < 2; ++pf)
            #pragma unroll
            for (int nb = 0; nb < 2; ++nb) {
                bh[pf][nb] = BH[(pf * 16 + nb) * 32];
                bl[pf][nb] = BL[(pf * 16 + nb) * 32];
            }
        #pragma unroll
        for (int kb = 0; kb < 16; ++kb) {
            const int cur = kb % 3;
            if (kb < 14) {
                const int dst = (kb + 2) % 3;
                #pragma unroll
                for (int nb = 0; nb < 2; ++nb) {
                    bh[dst][nb] = BH[((kb + 2) * 16 + nb) * 32];
                    bl[dst][nb] = BL[((kb + 2) * 16 + nb) * 32];
                }
            }
            #pragma unroll
            for (int mb = 0; mb < 4; ++mb) {
                uint32_t ah[4];
                ldm_x4(ah, ash + abase + mb * 16 * AS1 + kb * 32);
                #pragma unroll
                for (int nb = 0; nb < 2; ++nb) {
                    mma_f16(acc[mb][nb], ah, bh[cur][nb].x, bh[cur][nb].y);
                    mma_f16(acc[mb][nb], ah, bl[cur][nb].x, bl[cur][nb].y);
                }
            }
        }

        // ---- fused epilogue for this 128-col tile ----
        #pragma unroll
        for (int mb = 0; mb < 4; ++mb) {
            #pragma unroll
            for (int nb = 0; nb < 2; ++nb) {
                int cloc = (wn * 2 + nb) * 8 + (lane & 3) * 2;
                float bx = sbias[nt * 128 + cloc];
                float by = sbias[nt * 128 + cloc + 1];
                int lr0 = wm * 64 + mb * 16 + (lane >> 2);
                size_t r0 = row0 + lr0, r1 = r0 + 8;
                float y0 = acc[mb][nb][0] + bx;
                float y1 = acc[mb][nb][1] + by;
                float y2 = acc[mb][nb][2] + bx;
                float y3 = acc[mb][nb][3] + by;
                if (nt < 2) {
                    int ch = nt * 64 + (cloc >> 1);
                    g_a[r0 * CCH + ch] = sigf(y0) * y1;
                    g_a[r1 * CCH + ch] = sigf(y2) * y3;
                } else if (nt < 4) {
                    int ch = (nt - 2) * 64 + (cloc >> 1);
                    int c0 = (cls0 + lr0) % KGRP;
                    int c1 = (cls0 + lr0 + 8) % KGRP;
                    atomicAdd(&sBp[c0 * CCH + ch], sigf(y0) * y1);
                    atomicAdd(&sBp[c1 * CCH + ch], sigf(y2) * y3);
                } else {
                    int cg = (nt - 4) * 128 + cloc;
                    *(float2*)(g_gate + r0 * CIN + cg) = make_float2(sigf(y0), sigf(y1));
                    *(float2*)(g_gate + r1 * CIN + cg) = make_float2(sigf(y2), sigf(y3));
                }
            }
        }
    }
    __syncthreads();
    for (int i = tid; i < KGRP * CCH; i += NTHR)
        g_Bpart[(size_t)blockIdx.x * (KGRP * CCH) + i] = sBp[i];
}

// ---------------- reduce B partials: 2-stage, deterministic ----------------
__global__ void k_redB1() {          // grid (6, 25)
    int d = blockIdx.x * 256 + threadIdx.x;
    int b0 = blockIdx.y * 75;
    float s = 0.0f;
    for (int b = b0; b < b0 + 75; ++b) s += g_Bpart[(size_t)b * (KGRP * CCH) + d];
    g_B2[blockIdx.y * (KGRP * CCH) + d] = s;
}
__global__ void k_redB2() {          // grid 6
    int d = blockIdx.x * 256 + threadIdx.x;
    float s = 0.0f;
    for (int y = 0; y < 25; ++y) s += g_B2[y * (KGRP * CCH) + d];
    g_B[d] = s;
}

// ---------------- kernel 2: tri + LN + out GEMM (256 cols) + gate ----------------
__global__ void __launch_bounds__(NTHR, 1)
k_mma2(const float* __restrict__ lnog, const float* __restrict__ lnob,
       const float* __restrict__ blo, float* __restrict__ out) {
    extern __shared__ char sm[];
    char*  Ash = sm;
    float* Bsm = (float*)(sm + SM2_B);

    const int tid  = threadIdx.x;
    const int lane = tid & 31;
    const int wid  = tid >> 5;
    const int wm   = wid >> 3;    // 0..1
    const int wn   = wid & 7;     // 0..7
    const size_t row0 = (size_t)blockIdx.x * MT;

    for (int i = tid; i < KGRP * CCH; i += NTHR) Bsm[i] = g_B[i];
    __syncthreads();

    // ---- tri = a * B[row%12], LN over 128, fp16 into smem ----
    {
        float4 g4 = *(const float4*)(lnog + lane * 4);
        float4 b4 = *(const float4*)(lnob + lane * 4);
        for (int rr = 0; rr < 8; ++rr) {
            int r = wid * 8 + rr;
            size_t gr = row0 + r;
            float4 av = *(const float4*)(g_a + gr * CCH + lane * 4);
            const float* Br = Bsm + (int)(gr % KGRP) * CCH;
            float4 bv = *(const float4*)(Br + lane * 4);
            float t0 = av.x*bv.x, t1 = av.y*bv.y, t2 = av.z*bv.z, t3 = av.w*bv.w;
            float s = t0 + t1 + t2 + t3;
            float q = t0*t0 + t1*t1 + t2*t2 + t3*t3;
            #pragma unroll
            for (int o = 16; o; o >>= 1) {
                s += __shfl_xor_sync(0xffffffffu, s, o);
                q += __shfl_xor_sync(0xffffffffu, q, o);
            }
            float mu  = s * (1.0f / 128.0f);
            float var = fmaxf(q * (1.0f / 128.0f) - mu * mu, 0.0f);
            float rs  = rsqrtf(var + 1e-5f);
            float x0 = (t0 - mu) * rs * g4.x + b4.x;
            float x1 = (t1 - mu) * rs * g4.y + b4.y;
            float x2 = (t2 - mu) * rs * g4.z + b4.z;
            float x3 = (t3 - mu) * rs * g4.w + b4.w;
            *(uint2*)(Ash + r*AS2 + lane*8) = make_uint2(pk(x0,x1), pk(x2,x3));
        }
    }
    __syncthreads();

    const uint32_t ash = smem_u32(Ash);
    const int lrow = (lane & 7) + ((lane >> 3) & 1) * 8;
    const int lkof = ((lane >> 4) & 1) * 16;
    const uint32_t abase = (uint32_t)((wm * 64 + lrow) * AS2 + lkof);

    #pragma unroll 1
    for (int nt = 0; nt < 2; ++nt) {
        float acc[4][2][4];
        #pragma unroll
        for (int mb = 0; mb < 4; ++mb)
            #pragma unroll
            for (int nb = 0; nb < 2; ++nb)
                #pragma unroll
                for (int e = 0; e < 4; ++e) acc[mb][nb][e] = 0.0f;

        const uint2* __restrict__ BH = ((const uint2*)g_W2h) + ((size_t)(nt*8)*16 + wn*2)*32 + lane;
        const uint2* __restrict__ BL = ((const uint2*)g_W2l) + ((size_t)(nt*8)*16 + wn*2)*32 + lane;

        uint2 bh[3][2], bl[3][2];
        #pragma unroll
        for (int pf = 0; pf < 2; ++pf)
            #pragma unroll
            for (int nb = 0; nb < 2; ++nb) {
                bh[pf][nb] = BH[(pf * 16 + nb) * 32];
                bl[pf][nb] = BL[(pf * 16 + nb) * 32];
            }
        #pragma unroll
        for (int kb = 0; kb < 8; ++kb) {
            const int cur = kb % 3;
            if (kb < 6) {
                const int dst = (kb + 2) % 3;
                #pragma unroll
                for (int nb = 0; nb < 2; ++nb) {
                    bh[dst][nb] = BH[((kb + 2) * 16 + nb) * 32];
                    bl[dst][nb] = BL[((kb + 2) * 16 + nb) * 32];
                }
            }
            #pragma unroll
            for (int mb = 0; mb < 4; ++mb) {
                uint32_t ah[4];
                ldm_x4(ah, ash + abase + mb * 16 * AS2 + kb * 32);
                #pragma unroll
                for (int nb = 0; nb < 2; ++nb) {
                    mma_f16(acc[mb][nb], ah, bh[cur][nb].x, bh[cur][nb].y);
                    mma_f16(acc[mb][nb], ah, bl[cur][nb].x, bl[cur][nb].y);
                }
            }
        }

        // ---- epilogue: out = gate * (acc + blo) ----
        #pragma unroll
        for (int mb = 0; mb < 4; ++mb) {
            #pragma unroll
            for (int nb = 0; nb < 2; ++nb) {
                int c = nt * 128 + (wn * 2 + nb) * 8 + (lane & 3) * 2;
                float2 bias = *(const float2*)(blo + c);
                size_t r0 = row0 + wm * 64 + mb * 16 + (lane >> 2), r1 = r0 + 8;
                float2 gt0 = *(const float2*)(g_gate + r0 * CIN + c);
                float2 gt1 = *(const float2*)(g_gate + r1 * CIN + c);
                *(float2*)(out + r0 * CIN + c) =
                    make_float2(gt0.x * (acc[mb][nb][0] + bias.x),
                                gt0.y * (acc[mb][nb][1] + bias.y));
                *(float2*)(out + r1 * CIN + c) =
                    make_float2(gt1.x * (acc[mb][nb][2] + bias.x),
                                gt1.y * (acc[mb][nb][3] + bias.y));
            }
        }
    }
}

// ---------------- launch ----------------
extern "C" void kernel_launch(void* const* d_in, const int* in_sizes, int n_in,
                              void* d_out, int out_size) {
    const float* values  = (const float*)d_in[0];
    const float* ln_in_g = (const float*)d_in[1];
    const float* ln_in_b = (const float*)d_in[2];
    const float* W_ga    = (const float*)d_in[3];
    const float* b_ga    = (const float*)d_in[4];
    const float* W_la    = (const float*)d_in[5];
    const float* b_la    = (const float*)d_in[6];
    const float* W_gb    = (const float*)d_in[7];
    const float* b_gb    = (const float*)d_in[8];
    const float* W_lb    = (const float*)d_in[9];
    const float* b_lb    = (const float*)d_in[10];
    const float* ln_o_g  = (const float*)d_in[11];
    const float* ln_o_b  = (const float*)d_in[12];
    const float* W_go    = (const float*)d_in[13];
    const float* b_go    = (const float*)d_in[14];
    const float* W_lo    = (const float*)d_in[15];
    const float* b_lo    = (const float*)d_in[16];
    float* out = (float*)d_out;

    cudaFuncSetAttribute(k_mma1, cudaFuncAttributeMaxDynamicSharedMemorySize, SM1_TOTAL);
    cudaFuncSetAttribute(k_mma2, cudaFuncAttributeMaxDynamicSharedMemorySize, SM2_TOTAL);

    int pack_threads = 98304 + 16384 + 768;
    k_pack<<<(pack_threads + 255) / 256, 256>>>(W_ga, b_ga, W_la, b_la,
                                                W_gb, b_gb, W_lb, b_lb,
                                                W_go, b_go, W_lo);
    k_mma1<<<NRB1, NTHR, SM1_TOTAL>>>(values, ln_in_g, ln_in_b);
    k_redB1<<<dim3(6, 25), 256>>>();
    k_redB2<<<6, 256>>>();
    k_mma2<<<NRB1, NTHR, SM2_TOTAL>>>(ln_o_g, ln_o_b, b_lo, out);
}

// round 9
// speedup vs baseline: 4.5331x; 1.0830x over previous
#include <cuda_runtime.h>
#include <cuda_fp16.h>
#include <math.h>
#include <stdint.h>

// ---------------- problem constants ----------------
#define NNZ   240000
#define CIN   256
#define CCH   128
#define KGRP  12
#define MT    128
#define NRB1  (NNZ / MT)          // 1875
#define NTHR  512

#define AS1   528                 // A smem row stride bytes (K=256 fp16 + 16B pad)
#define AS2   272                 // K=128 fp16 + 16B pad

// smem layout k_mma1 (bytes)
#define SM1_BP    (128 * AS1)
#define SM1_BIAS  (SM1_BP + KGRP * CCH * 4)
#define SM1_TOTAL (SM1_BIAS + 768 * 4)      // 76800
// smem layout k_mma2
#define SM2_B     (128 * AS2)
#define SM2_TOTAL (SM2_B + KGRP * CCH * 4)  // 40960

// ---------------- device scratch ----------------
__device__ __align__(16) uint32_t g_Wfh[6 * 16 * 16 * 64];   // big-GEMM B frags hi (fp16)
__device__ __align__(16) uint32_t g_Wfl[6 * 16 * 16 * 64];   // lo residual (fp16)
__device__ __align__(16) uint32_t g_W2h[2 * 8 * 16 * 64];    // out-GEMM B frags hi
__device__ __align__(16) uint32_t g_W2l[2 * 8 * 16 * 64];
__device__ float g_bcat[768];                                // pair-interleaved bias
__device__ float g_a[(size_t)NNZ * CCH];
__device__ float g_gate[(size_t)NNZ * CIN];
__device__ float g_Bpart[(size_t)NRB1 * KGRP * CCH];
__device__ float g_B2[25 * KGRP * CCH];
__device__ float g_B[KGRP * CCH];

__device__ __forceinline__ float sigf(float x) { return 1.0f / (1.0f + expf(-x)); }

__device__ __forceinline__ uint32_t smem_u32(const void* p) {
    uint32_t a;
    asm("{ .reg .u64 t; cvta.to.shared.u64 t, %1; cvt.u32.u64 %0, t; }" : "=r"(a) : "l"(p));
    return a;
}
__device__ __forceinline__ void ldm_x4(uint32_t* r, uint32_t addr) {
    asm volatile("ldmatrix.sync.aligned.m8n8.x4.shared.b16 {%0,%1,%2,%3}, [%4];"
        : "=r"(r[0]), "=r"(r[1]), "=r"(r[2]), "=r"(r[3]) : "r"(addr));
}
__device__ __forceinline__ void mma_f16(float* d, const uint32_t* a, uint32_t b0, uint32_t b1) {
    asm volatile("mma.sync.aligned.m16n8k16.row.col.f32.f16.f16.f32 "
        "{%0,%1,%2,%3}, {%4,%5,%6,%7}, {%8,%9}, {%0,%1,%2,%3};"
        : "+f"(d[0]), "+f"(d[1]), "+f"(d[2]), "+f"(d[3])
        : "r"(a[0]), "r"(a[1]), "r"(a[2]), "r"(a[3]), "r"(b0), "r"(b1));
}
__device__ __forceinline__ uint32_t pk(float a, float b) {
    __half2 h = __floats2half2_rn(a, b);
    return *(uint32_t*)&h;
}
__device__ __forceinline__ float fph(float x) {
    return __half2float(__float2half_rn(x));
}

// ---------------- shared mainloop: one 128-row x 16-col warp tile over K ----------------
// LO=1: two passes (hi + lo residual of B); LO=0: single pass.
template<int NKB, int LO>
__device__ __forceinline__ void gemm_tile(float acc[4][2][4],
                                          uint32_t abase, int astride,
                                          const uint2* __restrict__ BH,
                                          const uint2* __restrict__ BL) {
    uint2 bh[3][2], bl[3][2];
    #pragma unroll
    for (int pf = 0; pf < 2; ++pf)
        #pragma unroll
        for (int nb = 0; nb < 2; ++nb) {
            bh[pf][nb] = BH[(pf * 16 + nb) * 32];
            if (LO) bl[pf][nb] = BL[(pf * 16 + nb) * 32];
        }
    #pragma unroll
    for (int kb = 0; kb < NKB; ++kb) {
        const int cur = kb % 3;
        if (kb < NKB - 2) {
            const int dst = (kb + 2) % 3;
            #pragma unroll
            for (int nb = 0; nb < 2; ++nb) {
                bh[dst][nb] = BH[((kb + 2) * 16 + nb) * 32];
                if (LO) bl[dst][nb] = BL[((kb + 2) * 16 + nb) * 32];
            }
        }
        #pragma unroll
        for (int mb = 0; mb < 4; ++mb) {
            uint32_t ah[4];
            ldm_x4(ah, abase + mb * 16 * astride + kb * 32);
            #pragma unroll
            for (int nb = 0; nb < 2; ++nb) {
                mma_f16(acc[mb][nb], ah, bh[cur][nb].x, bh[cur][nb].y);
                if (LO) mma_f16(acc[mb][nb], ah, bl[cur][nb].x, bl[cur][nb].y);
            }
        }
    }
}

// ---------------- kernel: pack weights into fragment-ordered fp16 hi/lo ----------------
__global__ void k_pack(const float* __restrict__ Wga, const float* __restrict__ bga,
                       const float* __restrict__ Wla, const float* __restrict__ bla,
                       const float* __restrict__ Wgb, const float* __restrict__ bgb,
                       const float* __restrict__ Wlb, const float* __restrict__ blb,
                       const float* __restrict__ Wgo, const float* __restrict__ bgo,
                       const float* __restrict__ Wlo) {
    int idx = blockIdx.x * blockDim.x + threadIdx.x;
    if (idx < 98304) {
        int lane2 = idx & 63, lane = lane2 >> 1, reg = lane2 & 1;
        int nb = (idx >> 6) & 15, kb = (idx >> 10) & 15, nt = idx >> 14;
        int k0 = kb * 16 + (lane & 3) * 2 + reg * 8;
        int p  = nt * 128 + nb * 8 + (lane >> 2);
        const float* W; int c;
        if (p < 256)      { c = p >> 1;                W = (p & 1) ? Wla : Wga; }
        else if (p < 512) { int q = p - 256; c = q >> 1; W = (q & 1) ? Wlb : Wgb; }
        else              { c = p - 512;               W = Wgo; }
        float w0 = W[c * CIN + k0], w1 = W[c * CIN + k0 + 1];
        float h0 = fph(w0), h1 = fph(w1);
        g_Wfh[idx] = pk(h0, h1);
        g_Wfl[idx] = pk(w0 - h0, w1 - h1);
    } else if (idx < 98304 + 16384) {
        int i2 = idx - 98304;
        int lane2 = i2 & 63, lane = lane2 >> 1, reg = lane2 & 1;
        int nb = (i2 >> 6) & 15, kb = (i2 >> 10) & 7, nt = i2 >> 13;
        int k0 = kb * 16 + (lane & 3) * 2 + reg * 8;
        int j  = nt * 128 + nb * 8 + (lane >> 2);
        float w0 = Wlo[j * CCH + k0], w1 = Wlo[j * CCH + k0 + 1];
        float h0 = fph(w0), h1 = fph(w1);
        g_W2h[i2] = pk(h0, h1);
        g_W2l[i2] = pk(w0 - h0, w1 - h1);
    } else if (idx < 98304 + 16384 + 768) {
        int p = idx - 98304 - 16384;
        float b;
        if (p < 256)      b = (p & 1) ? bla[p >> 1] : bga[p >> 1];
        else if (p < 512) { int q = p - 256; b = (q & 1) ? blb[q >> 1] : bgb[q >> 1]; }
        else              b = bgo[p - 512];
        g_bcat[p] = b;
    }
}

// ---------------- kernel 1: LN + big GEMM (768 cols) + fused epilogues ----------------
__global__ void __launch_bounds__(NTHR, 1)
k_mma1(const float* __restrict__ vals,
       const float* __restrict__ lng, const float* __restrict__ lnb) {
    extern __shared__ char sm[];
    char*  Ash   = sm;
    float* sBp   = (float*)(sm + SM1_BP);
    float* sbias = (float*)(sm + SM1_BIAS);

    const int tid  = threadIdx.x;
    const int lane = tid & 31;
    const int wid  = tid >> 5;
    const int wm   = wid >> 3;    // 0..1
    const int wn   = wid & 7;     // 0..7
    const size_t row0 = (size_t)blockIdx.x * MT;

    for (int i = tid; i < KGRP * CCH; i += NTHR) sBp[i] = 0.0f;
    for (int i = tid; i < 768; i += NTHR) sbias[i] = g_bcat[i];

    // ---- LN phase: 8 rows per warp, fp16 into smem A image ----
    {
        float4 g0 = *(const float4*)(lng + lane * 4);
        float4 g1 = *(const float4*)(lng + 128 + lane * 4);
        float4 b0 = *(const float4*)(lnb + lane * 4);
        float4 b1 = *(const float4*)(lnb + 128 + lane * 4);
        for (int rr = 0; rr < 8; ++rr) {
            int r = wid * 8 + rr;
            const float* vr = vals + (row0 + r) * CIN;
            float4 v0 = *(const float4*)(vr + lane * 4);
            float4 v1 = *(const float4*)(vr + 128 + lane * 4);
            float s = v0.x + v0.y + v0.z + v0.w + v1.x + v1.y + v1.z + v1.w;
            float q = v0.x*v0.x + v0.y*v0.y + v0.z*v0.z + v0.w*v0.w
                    + v1.x*v1.x + v1.y*v1.y + v1.z*v1.z + v1.w*v1.w;
            #pragma unroll
            for (int o = 16; o; o >>= 1) {
                s += __shfl_xor_sync(0xffffffffu, s, o);
                q += __shfl_xor_sync(0xffffffffu, q, o);
            }
            float mu  = s * (1.0f / 256.0f);
            float var = fmaxf(q * (1.0f / 256.0f) - mu * mu, 0.0f);
            float rs  = rsqrtf(var + 1e-5f);
            float x[8];
            x[0]=(v0.x-mu)*rs*g0.x+b0.x; x[1]=(v0.y-mu)*rs*g0.y+b0.y;
            x[2]=(v0.z-mu)*rs*g0.z+b0.z; x[3]=(v0.w-mu)*rs*g0.w+b0.w;
            x[4]=(v1.x-mu)*rs*g1.x+b1.x; x[5]=(v1.y-mu)*rs*g1.y+b1.y;
            x[6]=(v1.z-mu)*rs*g1.z+b1.z; x[7]=(v1.w-mu)*rs*g1.w+b1.w;
            *(uint2*)(Ash + r*AS1 + lane*8)       = make_uint2(pk(x[0],x[1]), pk(x[2],x[3]));
            *(uint2*)(Ash + r*AS1 + 256 + lane*8) = make_uint2(pk(x[4],x[5]), pk(x[6],x[7]));
        }
    }
    __syncthreads();

    const uint32_t ash = smem_u32(Ash);
    const int lrow = (lane & 7) + ((lane >> 3) & 1) * 8;
    const int lkof = ((lane >> 4) & 1) * 16;
    const uint32_t abase = ash + (uint32_t)((wm * 64 + lrow) * AS1 + lkof);
    const int cls0 = (int)(row0 % KGRP);

    #pragma unroll 1
    for (int nt = 0; nt < 6; ++nt) {
        float acc[4][2][4];
        #pragma unroll
        for (int mb = 0; mb < 4; ++mb)
            #pragma unroll
            for (int nb = 0; nb < 2; ++nb)
                #pragma unroll
                for (int e = 0; e < 4; ++e) acc[mb][nb][e] = 0.0f;

        const uint2* __restrict__ BH = ((const uint2*)g_Wfh) + ((size_t)(nt*16)*16 + wn*2)*32 + lane;
        const uint2* __restrict__ BL = ((const uint2*)g_Wfl) + ((size_t)(nt*16)*16 + wn*2)*32 + lane;

        if (nt < 2) gemm_tile<16, 1>(acc, abase, AS1, BH, BL);   // a-path: 2-pass
        else        gemm_tile<16, 0>(acc, abase, AS1, BH, BL);   // b/gate: 1-pass

        // ---- fused epilogue for this 128-col tile ----
        #pragma unroll
        for (int mb = 0; mb < 4; ++mb) {
            #pragma unroll
            for (int nb = 0; nb < 2; ++nb) {
                int cloc = (wn * 2 + nb) * 8 + (lane & 3) * 2;
                float bx = sbias[nt * 128 + cloc];
                float by = sbias[nt * 128 + cloc + 1];
                int lr0 = wm * 64 + mb * 16 + (lane >> 2);
                size_t r0 = row0 + lr0, r1 = r0 + 8;
                float y0 = acc[mb][nb][0] + bx;
                float y1 = acc[mb][nb][1] + by;
                float y2 = acc[mb][nb][2] + bx;
                float y3 = acc[mb][nb][3] + by;
                if (nt < 2) {
                    int ch = nt * 64 + (cloc >> 1);
                    g_a[r0 * CCH + ch] = sigf(y0) * y1;
                    g_a[r1 * CCH + ch] = sigf(y2) * y3;
                } else if (nt < 4) {
                    int ch = (nt - 2) * 64 + (cloc >> 1);
                    int c0 = (cls0 + lr0) % KGRP;
                    int c1 = (cls0 + lr0 + 8) % KGRP;
                    atomicAdd(&sBp[c0 * CCH + ch], sigf(y0) * y1);
                    atomicAdd(&sBp[c1 * CCH + ch], sigf(y2) * y3);
                } else {
                    int cg = (nt - 4) * 128 + cloc;
                    *(float2*)(g_gate + r0 * CIN + cg) = make_float2(sigf(y0), sigf(y1));
                    *(float2*)(g_gate + r1 * CIN + cg) = make_float2(sigf(y2), sigf(y3));
                }
            }
        }
    }
    __syncthreads();
    for (int i = tid; i < KGRP * CCH; i += NTHR)
        g_Bpart[(size_t)blockIdx.x * (KGRP * CCH) + i] = sBp[i];
}

// ---------------- reduce B partials: 2-stage, deterministic ----------------
__global__ void k_redB1() {          // grid (6, 25)
    int d = blockIdx.x * 256 + threadIdx.x;
    int b0 = blockIdx.y * 75;
    float s = 0.0f;
    for (int b = b0; b < b0 + 75; ++b) s += g_Bpart[(size_t)b * (KGRP * CCH) + d];
    g_B2[blockIdx.y * (KGRP * CCH) + d] = s;
}
__global__ void k_redB2() {          // grid 6
    int d = blockIdx.x * 256 + threadIdx.x;
    float s = 0.0f;
    for (int y = 0; y < 25; ++y) s += g_B2[y * (KGRP * CCH) + d];
    g_B[d] = s;
}

// ---------------- kernel 2: tri + LN + out GEMM (256 cols) + gate ----------------
__global__ void __launch_bounds__(NTHR, 1)
k_mma2(const float* __restrict__ lnog, const float* __restrict__ lnob,
       const float* __restrict__ blo, float* __restrict__ out) {
    extern __shared__ char sm[];
    char*  Ash = sm;
    float* Bsm = (float*)(sm + SM2_B);

    const int tid  = threadIdx.x;
    const int lane = tid & 31;
    const int wid  = tid >> 5;
    const int wm   = wid >> 3;    // 0..1
    const int wn   = wid & 7;     // 0..7
    const size_t row0 = (size_t)blockIdx.x * MT;

    for (int i = tid; i < KGRP * CCH; i += NTHR) Bsm[i] = g_B[i];
    __syncthreads();

    // ---- tri = a * B[row%12], LN over 128, fp16 into smem ----
    {
        float4 g4 = *(const float4*)(lnog + lane * 4);
        float4 b4 = *(const float4*)(lnob + lane * 4);
        for (int rr = 0; rr < 8; ++rr) {
            int r = wid * 8 + rr;
            size_t gr = row0 + r;
            float4 av = *(const float4*)(g_a + gr * CCH + lane * 4);
            const float* Br = Bsm + (int)(gr % KGRP) * CCH;
            float4 bv = *(const float4*)(Br + lane * 4);
            float t0 = av.x*bv.x, t1 = av.y*bv.y, t2 = av.z*bv.z, t3 = av.w*bv.w;
            float s = t0 + t1 + t2 + t3;
            float q = t0*t0 + t1*t1 + t2*t2 + t3*t3;
            #pragma unroll
            for (int o = 16; o; o >>= 1) {
                s += __shfl_xor_sync(0xffffffffu, s, o);
                q += __shfl_xor_sync(0xffffffffu, q, o);
            }
            float mu  = s * (1.0f / 128.0f);
            float var = fmaxf(q * (1.0f / 128.0f) - mu * mu, 0.0f);
            float rs  = rsqrtf(var + 1e-5f);
            float x0 = (t0 - mu) * rs * g4.x + b4.x;
            float x1 = (t1 - mu) * rs * g4.y + b4.y;
            float x2 = (t2 - mu) * rs * g4.z + b4.z;
            float x3 = (t3 - mu) * rs * g4.w + b4.w;
            *(uint2*)(Ash + r*AS2 + lane*8) = make_uint2(pk(x0,x1), pk(x2,x3));
        }
    }
    __syncthreads();

    const uint32_t ash = smem_u32(Ash);
    const int lrow = (lane & 7) + ((lane >> 3) & 1) * 8;
    const int lkof = ((lane >> 4) & 1) * 16;
    const uint32_t abase = ash + (uint32_t)((wm * 64 + lrow) * AS2 + lkof);

    #pragma unroll 1
    for (int nt = 0; nt < 2; ++nt) {
        float acc[4][2][4];
        #pragma unroll
        for (int mb = 0; mb < 4; ++mb)
            #pragma unroll
            for (int nb = 0; nb < 2; ++nb)
                #pragma unroll
                for (int e = 0; e < 4; ++e) acc[mb][nb][e] = 0.0f;

        const uint2* __restrict__ BH = ((const uint2*)g_W2h) + ((size_t)(nt*8)*16 + wn*2)*32 + lane;
        const uint2* __restrict__ BL = ((const uint2*)g_W2l) + ((size_t)(nt*8)*16 + wn*2)*32 + lane;

        gemm_tile<8, 1>(acc, abase, AS2, BH, BL);   // final linear: 2-pass

        // ---- epilogue: out = gate * (acc + blo) ----
        #pragma unroll
        for (int mb = 0; mb < 4; ++mb) {
            #pragma unroll
            for (int nb = 0; nb < 2; ++nb) {
                int c = nt * 128 + (wn * 2 + nb) * 8 + (lane & 3) * 2;
                float2 bias = *(const float2*)(blo + c);
                size_t r0 = row0 + wm * 64 + mb * 16 + (lane >> 2), r1 = r0 + 8;
                float2 gt0 = *(const float2*)(g_gate + r0 * CIN + c);
                float2 gt1 = *(const float2*)(g_gate + r1 * CIN + c);
                *(float2*)(out + r0 * CIN + c) =
                    make_float2(gt0.x * (acc[mb][nb][0] + bias.x),
                                gt0.y * (acc[mb][nb][1] + bias.y));
                *(float2*)(out + r1 * CIN + c) =
                    make_float2(gt1.x * (acc[mb][nb][2] + bias.x),
                                gt1.y * (acc[mb][nb][3] + bias.y));
            }
        }
    }
}

// ---------------- launch ----------------
extern "C" void kernel_launch(void* const* d_in, const int* in_sizes, int n_in,
                              void* d_out, int out_size) {
    const float* values  = (const float*)d_in[0];
    const float* ln_in_g = (const float*)d_in[1];
    const float* ln_in_b = (const float*)d_in[2];
    const float* W_ga    = (const float*)d_in[3];
    const float* b_ga    = (const float*)d_in[4];
    const float* W_la    = (const float*)d_in[5];
    const float* b_la    = (const float*)d_in[6];
    const float* W_gb    = (const float*)d_in[7];
    const float* b_gb    = (const float*)d_in[8];
    const float* W_lb    = (const float*)d_in[9];
    const float* b_lb    = (const float*)d_in[10];
    const float* ln_o_g  = (const float*)d_in[11];
    const float* ln_o_b  = (const float*)d_in[12];
    const float* W_go    = (const float*)d_in[13];
    const float* b_go    = (const float*)d_in[14];
    const float* W_lo    = (const float*)d_in[15];
    const float* b_lo    = (const float*)d_in[16];
    float* out = (float*)d_out;

    cudaFuncSetAttribute(k_mma1, cudaFuncAttributeMaxDynamicSharedMemorySize, SM1_TOTAL);
    cudaFuncSetAttribute(k_mma2, cudaFuncAttributeMaxDynamicSharedMemorySize, SM2_TOTAL);

    int pack_threads = 98304 + 16384 + 768;
    k_pack<<<(pack_threads + 255) / 256, 256>>>(W_ga, b_ga, W_la, b_la,
                                                W_gb, b_gb, W_lb, b_lb,
                                                W_go, b_go, W_lo);
    k_mma1<<<NRB1, NTHR, SM1_TOTAL>>>(values, ln_in_g, ln_in_b);
    k_redB1<<<dim3(6, 25), 256>>>();
    k_redB2<<<6, 256>>>();
    k_mma2<<<NRB1, NTHR, SM2_TOTAL>>>(ln_o_g, ln_o_b, b_lo, out);
}

// round 10
// speedup vs baseline: 5.1768x; 1.1420x over previous
#include <cuda_runtime.h>
#include <cuda_fp16.h>
#include <math.h>
#include <stdint.h>

// ---------------- problem constants ----------------
#define NNZ   240000
#define CIN   256
#define CCH   128
#define KGRP  12
#define MT    128
#define NRB1  (NNZ / MT)          // 1875
#define NTHR  512

#define AS1   528                 // A smem row stride bytes (K=256 fp16 + 16B pad)
#define AS2   272                 // K=128 fp16 + 16B pad

// smem layout k_mma1 (bytes)
#define SM1_BP    (128 * AS1)
#define SM1_BIAS  (SM1_BP + KGRP * CCH * 4)
#define SM1_TOTAL (SM1_BIAS + 768 * 4)      // 76800
// smem layout k_mma2
#define SM2_B     (128 * AS2)
#define SM2_TOTAL (SM2_B + KGRP * CCH * 4)  // 40960

// ---------------- device scratch ----------------
__device__ __align__(16) uint32_t g_Wfh[6 * 16 * 16 * 64];   // big-GEMM B frags hi (fp16)
__device__ __align__(16) uint32_t g_Wfl[6 * 16 * 16 * 64];   // lo residual (unused for k_mma1 now)
__device__ __align__(16) uint32_t g_W2h[2 * 8 * 16 * 64];    // out-GEMM B frags hi
__device__ __align__(16) uint32_t g_W2l[2 * 8 * 16 * 64];
__device__ float g_bcat[768];                                // pair-interleaved bias
__device__ float g_a[(size_t)NNZ * CCH];
__device__ float g_gate[(size_t)NNZ * CIN];
__device__ float g_Bpart[(size_t)NRB1 * KGRP * CCH];
__device__ float g_B2[25 * KGRP * CCH];
__device__ float g_B[KGRP * CCH];

__device__ __forceinline__ float sigf(float x) { return 1.0f / (1.0f + expf(-x)); }

__device__ __forceinline__ uint32_t smem_u32(const void* p) {
    uint32_t a;
    asm("{ .reg .u64 t; cvta.to.shared.u64 t, %1; cvt.u32.u64 %0, t; }" : "=r"(a) : "l"(p));
    return a;
}
__device__ __forceinline__ void ldm_x4(uint32_t* r, uint32_t addr) {
    asm volatile("ldmatrix.sync.aligned.m8n8.x4.shared.b16 {%0,%1,%2,%3}, [%4];"
        : "=r"(r[0]), "=r"(r[1]), "=r"(r[2]), "=r"(r[3]) : "r"(addr));
}
__device__ __forceinline__ void mma_f16(float* d, const uint32_t* a, uint32_t b0, uint32_t b1) {
    asm volatile("mma.sync.aligned.m16n8k16.row.col.f32.f16.f16.f32 "
        "{%0,%1,%2,%3}, {%4,%5,%6,%7}, {%8,%9}, {%0,%1,%2,%3};"
        : "+f"(d[0]), "+f"(d[1]), "+f"(d[2]), "+f"(d[3])
        : "r"(a[0]), "r"(a[1]), "r"(a[2]), "r"(a[3]), "r"(b0), "r"(b1));
}
__device__ __forceinline__ uint32_t pk(float a, float b) {
    __half2 h = __floats2half2_rn(a, b);
    return *(uint32_t*)&h;
}
__device__ __forceinline__ float fph(float x) {
    return __half2float(__float2half_rn(x));
}

// ---------------- paired mainloop: two 128x16 warp tiles share A fragments ----------------
__device__ __forceinline__ void gemm_pair(float acc[2][4][2][4],
                                          uint32_t abase,
                                          const uint2* __restrict__ B0,
                                          const uint2* __restrict__ B1) {
    uint2 b[3][2][2];     // [buf][tile][nb]
    #pragma unroll
    for (int pf = 0; pf < 2; ++pf)
        #pragma unroll
        for (int nb = 0; nb < 2; ++nb) {
            b[pf][0][nb] = B0[(pf * 16 + nb) * 32];
            b[pf][1][nb] = B1[(pf * 16 + nb) * 32];
        }
    #pragma unroll
    for (int kb = 0; kb < 16; ++kb) {
        const int cur = kb % 3;
        if (kb < 14) {
            const int dst = (kb + 2) % 3;
            #pragma unroll
            for (int nb = 0; nb < 2; ++nb) {
                b[dst][0][nb] = B0[((kb + 2) * 16 + nb) * 32];
                b[dst][1][nb] = B1[((kb + 2) * 16 + nb) * 32];
            }
        }
        #pragma unroll
        for (int mb = 0; mb < 4; ++mb) {
            uint32_t ah[4];
            ldm_x4(ah, abase + mb * 16 * AS1 + kb * 32);
            #pragma unroll
            for (int t = 0; t < 2; ++t)
                #pragma unroll
                for (int nb = 0; nb < 2; ++nb)
                    mma_f16(acc[t][mb][nb], ah, b[cur][t][nb].x, b[cur][t][nb].y);
        }
    }
}

// ---------------- single-tile mainloop (k_mma2, 2-pass) ----------------
template<int NKB, int LO>
__device__ __forceinline__ void gemm_tile(float acc[4][2][4],
                                          uint32_t abase, int astride,
                                          const uint2* __restrict__ BH,
                                          const uint2* __restrict__ BL) {
    uint2 bh[3][2], bl[3][2];
    #pragma unroll
    for (int pf = 0; pf < 2; ++pf)
        #pragma unroll
        for (int nb = 0; nb < 2; ++nb) {
            bh[pf][nb] = BH[(pf * 16 + nb) * 32];
            if (LO) bl[pf][nb] = BL[(pf * 16 + nb) * 32];
        }
    #pragma unroll
    for (int kb = 0; kb < NKB; ++kb) {
        const int cur = kb % 3;
        if (kb < NKB - 2) {
            const int dst = (kb + 2) % 3;
            #pragma unroll
            for (int nb = 0; nb < 2; ++nb) {
                bh[dst][nb] = BH[((kb + 2) * 16 + nb) * 32];
                if (LO) bl[dst][nb] = BL[((kb + 2) * 16 + nb) * 32];
            }
        }
        #pragma unroll
        for (int mb = 0; mb < 4; ++mb) {
            uint32_t ah[4];
            ldm_x4(ah, abase + mb * 16 * astride + kb * 32);
            #pragma unroll
            for (int nb = 0; nb < 2; ++nb) {
                mma_f16(acc[mb][nb], ah, bh[cur][nb].x, bh[cur][nb].y);
                if (LO) mma_f16(acc[mb][nb], ah, bl[cur][nb].x, bl[cur][nb].y);
            }
        }
    }
}

// ---------------- kernel: pack weights into fragment-ordered fp16 hi/lo ----------------
__global__ void k_pack(const float* __restrict__ Wga, const float* __restrict__ bga,
                       const float* __restrict__ Wla, const float* __restrict__ bla,
                       const float* __restrict__ Wgb, const float* __restrict__ bgb,
                       const float* __restrict__ Wlb, const float* __restrict__ blb,
                       const float* __restrict__ Wgo, const float* __restrict__ bgo,
                       const float* __restrict__ Wlo) {
    int idx = blockIdx.x * blockDim.x + threadIdx.x;
    if (idx < 98304) {
        int lane2 = idx & 63, lane = lane2 >> 1, reg = lane2 & 1;
        int nb = (idx >> 6) & 15, kb = (idx >> 10) & 15, nt = idx >> 14;
        int k0 = kb * 16 + (lane & 3) * 2 + reg * 8;
        int p  = nt * 128 + nb * 8 + (lane >> 2);
        const float* W; int c;
        if (p < 256)      { c = p >> 1;                W = (p & 1) ? Wla : Wga; }
        else if (p < 512) { int q = p - 256; c = q >> 1; W = (q & 1) ? Wlb : Wgb; }
        else              { c = p - 512;               W = Wgo; }
        float w0 = W[c * CIN + k0], w1 = W[c * CIN + k0 + 1];
        float h0 = fph(w0), h1 = fph(w1);
        g_Wfh[idx] = pk(h0, h1);
        g_Wfl[idx] = pk(w0 - h0, w1 - h1);
    } else if (idx < 98304 + 16384) {
        int i2 = idx - 98304;
        int lane2 = i2 & 63, lane = lane2 >> 1, reg = lane2 & 1;
        int nb = (i2 >> 6) & 15, kb = (i2 >> 10) & 7, nt = i2 >> 13;
        int k0 = kb * 16 + (lane & 3) * 2 + reg * 8;
        int j  = nt * 128 + nb * 8 + (lane >> 2);
        float w0 = Wlo[j * CCH + k0], w1 = Wlo[j * CCH + k0 + 1];
        float h0 = fph(w0), h1 = fph(w1);
        g_W2h[i2] = pk(h0, h1);
        g_W2l[i2] = pk(w0 - h0, w1 - h1);
    } else if (idx < 98304 + 16384 + 768) {
        int p = idx - 98304 - 16384;
        float b;
        if (p < 256)      b = (p & 1) ? bla[p >> 1] : bga[p >> 1];
        else if (p < 512) { int q = p - 256; b = (q & 1) ? blb[q >> 1] : bgb[q >> 1]; }
        else              b = bgo[p - 512];
        g_bcat[p] = b;
    }
}

// ---------------- kernel 1: LN + big GEMM (768 cols, 3 tile-pairs) + fused epilogues ----------------
__global__ void __launch_bounds__(NTHR, 1)
k_mma1(const float* __restrict__ vals,
       const float* __restrict__ lng, const float* __restrict__ lnb) {
    extern __shared__ char sm[];
    char*  Ash   = sm;
    float* sBp   = (float*)(sm + SM1_BP);
    float* sbias = (float*)(sm + SM1_BIAS);

    const int tid  = threadIdx.x;
    const int lane = tid & 31;
    const int wid  = tid >> 5;
    const int wm   = wid >> 3;    // 0..1
    const int wn   = wid & 7;     // 0..7
    const size_t row0 = (size_t)blockIdx.x * MT;

    for (int i = tid; i < KGRP * CCH; i += NTHR) sBp[i] = 0.0f;
    for (int i = tid; i < 768; i += NTHR) sbias[i] = g_bcat[i];

    // ---- LN phase: 8 rows per warp, fp16 into smem A image ----
    {
        float4 g0 = *(const float4*)(lng + lane * 4);
        float4 g1 = *(const float4*)(lng + 128 + lane * 4);
        float4 b0 = *(const float4*)(lnb + lane * 4);
        float4 b1 = *(const float4*)(lnb + 128 + lane * 4);
        for (int rr = 0; rr < 8; ++rr) {
            int r = wid * 8 + rr;
            const float* vr = vals + (row0 + r) * CIN;
            float4 v0 = *(const float4*)(vr + lane * 4);
            float4 v1 = *(const float4*)(vr + 128 + lane * 4);
            float s = v0.x + v0.y + v0.z + v0.w + v1.x + v1.y + v1.z + v1.w;
            float q = v0.x*v0.x + v0.y*v0.y + v0.z*v0.z + v0.w*v0.w
                    + v1.x*v1.x + v1.y*v1.y + v1.z*v1.z + v1.w*v1.w;
            #pragma unroll
            for (int o = 16; o; o >>= 1) {
                s += __shfl_xor_sync(0xffffffffu, s, o);
                q += __shfl_xor_sync(0xffffffffu, q, o);
            }
            float mu  = s * (1.0f / 256.0f);
            float var = fmaxf(q * (1.0f / 256.0f) - mu * mu, 0.0f);
            float rs  = rsqrtf(var + 1e-5f);
            float x[8];
            x[0]=(v0.x-mu)*rs*g0.x+b0.x; x[1]=(v0.y-mu)*rs*g0.y+b0.y;
            x[2]=(v0.z-mu)*rs*g0.z+b0.z; x[3]=(v0.w-mu)*rs*g0.w+b0.w;
            x[4]=(v1.x-mu)*rs*g1.x+b1.x; x[5]=(v1.y-mu)*rs*g1.y+b1.y;
            x[6]=(v1.z-mu)*rs*g1.z+b1.z; x[7]=(v1.w-mu)*rs*g1.w+b1.w;
            *(uint2*)(Ash + r*AS1 + lane*8)       = make_uint2(pk(x[0],x[1]), pk(x[2],x[3]));
            *(uint2*)(Ash + r*AS1 + 256 + lane*8) = make_uint2(pk(x[4],x[5]), pk(x[6],x[7]));
        }
    }
    __syncthreads();

    const uint32_t ash = smem_u32(Ash);
    const int lrow = (lane & 7) + ((lane >> 3) & 1) * 8;
    const int lkof = ((lane >> 4) & 1) * 16;
    const uint32_t abase = ash + (uint32_t)((wm * 64 + lrow) * AS1 + lkof);
    const int cls0 = (int)(row0 % KGRP);

    #pragma unroll 1
    for (int np = 0; np < 3; ++np) {      // pair (nt = 2np, 2np+1); np: 0=a, 1=b, 2=gate
        float acc[2][4][2][4];
        #pragma unroll
        for (int t = 0; t < 2; ++t)
            #pragma unroll
            for (int mb = 0; mb < 4; ++mb)
                #pragma unroll
                for (int nb = 0; nb < 2; ++nb)
                    #pragma unroll
                    for (int e = 0; e < 4; ++e) acc[t][mb][nb][e] = 0.0f;

        const uint2* __restrict__ B0 = ((const uint2*)g_Wfh) + ((size_t)((2*np    )*16)*16 + wn*2)*32 + lane;
        const uint2* __restrict__ B1 = ((const uint2*)g_Wfh) + ((size_t)((2*np + 1)*16)*16 + wn*2)*32 + lane;

        gemm_pair(acc, abase, B0, B1);

        // ---- fused epilogue for the two 128-col tiles of this pair ----
        #pragma unroll
        for (int t = 0; t < 2; ++t) {
            const int nt = 2 * np + t;
            #pragma unroll
            for (int mb = 0; mb < 4; ++mb) {
                #pragma unroll
                for (int nb = 0; nb < 2; ++nb) {
                    int cloc = (wn * 2 + nb) * 8 + (lane & 3) * 2;
                    float bx = sbias[nt * 128 + cloc];
                    float by = sbias[nt * 128 + cloc + 1];
                    int lr0 = wm * 64 + mb * 16 + (lane >> 2);
                    size_t r0 = row0 + lr0, r1 = r0 + 8;
                    float y0 = acc[t][mb][nb][0] + bx;
                    float y1 = acc[t][mb][nb][1] + by;
                    float y2 = acc[t][mb][nb][2] + bx;
                    float y3 = acc[t][mb][nb][3] + by;
                    if (np == 0) {
                        int ch = t * 64 + (cloc >> 1);
                        g_a[r0 * CCH + ch] = sigf(y0) * y1;
                        g_a[r1 * CCH + ch] = sigf(y2) * y3;
                    } else if (np == 1) {
                        int ch = t * 64 + (cloc >> 1);
                        int c0 = (cls0 + lr0) % KGRP;
                        int c1 = (cls0 + lr0 + 8) % KGRP;
                        atomicAdd(&sBp[c0 * CCH + ch], sigf(y0) * y1);
                        atomicAdd(&sBp[c1 * CCH + ch], sigf(y2) * y3);
                    } else {
                        int cg = t * 128 + cloc;
                        *(float2*)(g_gate + r0 * CIN + cg) = make_float2(sigf(y0), sigf(y1));
                        *(float2*)(g_gate + r1 * CIN + cg) = make_float2(sigf(y2), sigf(y3));
                    }
                }
            }
        }
    }
    __syncthreads();
    for (int i = tid; i < KGRP * CCH; i += NTHR)
        g_Bpart[(size_t)blockIdx.x * (KGRP * CCH) + i] = sBp[i];
}

// ---------------- reduce B partials: 2-stage, deterministic ----------------
__global__ void k_redB1() {          // grid (6, 25)
    int d = blockIdx.x * 256 + threadIdx.x;
    int b0 = blockIdx.y * 75;
    float s = 0.0f;
    for (int b = b0; b < b0 + 75; ++b) s += g_Bpart[(size_t)b * (KGRP * CCH) + d];
    g_B2[blockIdx.y * (KGRP * CCH) + d] = s;
}
__global__ void k_redB2() {          // grid 6
    int d = blockIdx.x * 256 + threadIdx.x;
    float s = 0.0f;
    for (int y = 0; y < 25; ++y) s += g_B2[y * (KGRP * CCH) + d];
    g_B[d] = s;
}

// ---------------- kernel 2: tri + LN + out GEMM (256 cols) + gate ----------------
__global__ void __launch_bounds__(NTHR, 1)
k_mma2(const float* __restrict__ lnog, const float* __restrict__ lnob,
       const float* __restrict__ blo, float* __restrict__ out) {
    extern __shared__ char sm[];
    char*  Ash = sm;
    float* Bsm = (float*)(sm + SM2_B);

    const int tid  = threadIdx.x;
    const int lane = tid & 31;
    const int wid  = tid >> 5;
    const int wm   = wid >> 3;    // 0..1
    const int wn   = wid & 7;     // 0..7
    const size_t row0 = (size_t)blockIdx.x * MT;

    for (int i = tid; i < KGRP * CCH; i += NTHR) Bsm[i] = g_B[i];
    __syncthreads();

    // ---- tri = a * B[row%12], LN over 128, fp16 into smem ----
    {
        float4 g4 = *(const float4*)(lnog + lane * 4);
        float4 b4 = *(const float4*)(lnob + lane * 4);
        for (int rr = 0; rr < 8; ++rr) {
            int r = wid * 8 + rr;
            size_t gr = row0 + r;
            float4 av = *(const float4*)(g_a + gr * CCH + lane * 4);
            const float* Br = Bsm + (int)(gr % KGRP) * CCH;
            float4 bv = *(const float4*)(Br + lane * 4);
            float t0 = av.x*bv.x, t1 = av.y*bv.y, t2 = av.z*bv.z, t3 = av.w*bv.w;
            float s = t0 + t1 + t2 + t3;
            float q = t0*t0 + t1*t1 + t2*t2 + t3*t3;
            #pragma unroll
            for (int o = 16; o; o >>= 1) {
                s += __shfl_xor_sync(0xffffffffu, s, o);
                q += __shfl_xor_sync(0xffffffffu, q, o);
            }
            float mu  = s * (1.0f / 128.0f);
            float var = fmaxf(q * (1.0f / 128.0f) - mu * mu, 0.0f);
            float rs  = rsqrtf(var + 1e-5f);
            float x0 = (t0 - mu) * rs * g4.x + b4.x;
            float x1 = (t1 - mu) * rs * g4.y + b4.y;
            float x2 = (t2 - mu) * rs * g4.z + b4.z;
            float x3 = (t3 - mu) * rs * g4.w + b4.w;
            *(uint2*)(Ash + r*AS2 + lane*8) = make_uint2(pk(x0,x1), pk(x2,x3));
        }
    }
    __syncthreads();

    const uint32_t ash = smem_u32(Ash);
    const int lrow = (lane & 7) + ((lane >> 3) & 1) * 8;
    const int lkof = ((lane >> 4) & 1) * 16;
    const uint32_t abase = ash + (uint32_t)((wm * 64 + lrow) * AS2 + lkof);

    #pragma unroll 1
    for (int nt = 0; nt < 2; ++nt) {
        float acc[4][2][4];
        #pragma unroll
        for (int mb = 0; mb < 4; ++mb)
            #pragma unroll
            for (int nb = 0; nb < 2; ++nb)
                #pragma unroll
                for (int e = 0; e < 4; ++e) acc[mb][nb][e] = 0.0f;

        const uint2* __restrict__ BH = ((const uint2*)g_W2h) + ((size_t)(nt*8)*16 + wn*2)*32 + lane;
        const uint2* __restrict__ BL = ((const uint2*)g_W2l) + ((size_t)(nt*8)*16 + wn*2)*32 + lane;

        gemm_tile<8, 1>(acc, abase, AS2, BH, BL);   // final linear: 2-pass

        // ---- epilogue: out = gate * (acc + blo) ----
        #pragma unroll
        for (int mb = 0; mb < 4; ++mb) {
            #pragma unroll
            for (int nb = 0; nb < 2; ++nb) {
                int c = nt * 128 + (wn * 2 + nb) * 8 + (lane & 3) * 2;
                float2 bias = *(const float2*)(blo + c);
                size_t r0 = row0 + wm * 64 + mb * 16 + (lane >> 2), r1 = r0 + 8;
                float2 gt0 = *(const float2*)(g_gate + r0 * CIN + c);
                float2 gt1 = *(const float2*)(g_gate + r1 * CIN + c);
                *(float2*)(out + r0 * CIN + c) =
                    make_float2(gt0.x * (acc[mb][nb][0] + bias.x),
                                gt0.y * (acc[mb][nb][1] + bias.y));
                *(float2*)(out + r1 * CIN + c) =
                    make_float2(gt1.x * (acc[mb][nb][2] + bias.x),
                                gt1.y * (acc[mb][nb][3] + bias.y));
            }
        }
    }
}

// ---------------- launch ----------------
extern "C" void kernel_launch(void* const* d_in, const int* in_sizes, int n_in,
                              void* d_out, int out_size) {
    const float* values  = (const float*)d_in[0];
    const float* ln_in_g = (const float*)d_in[1];
    const float* ln_in_b = (const float*)d_in[2];
    const float* W_ga    = (const float*)d_in[3];
    const float* b_ga    = (const float*)d_in[4];
    const float* W_la    = (const float*)d_in[5];
    const float* b_la    = (const float*)d_in[6];
    const float* W_gb    = (const float*)d_in[7];
    const float* b_gb    = (const float*)d_in[8];
    const float* W_lb    = (const float*)d_in[9];
    const float* b_lb    = (const float*)d_in[10];
    const float* ln_o_g  = (const float*)d_in[11];
    const float* ln_o_b  = (const float*)d_in[12];
    const float* W_go    = (const float*)d_in[13];
    const float* b_go    = (const float*)d_in[14];
    const float* W_lo    = (const float*)d_in[15];
    const float* b_lo    = (const float*)d_in[16];
    float* out = (float*)d_out;

    cudaFuncSetAttribute(k_mma1, cudaFuncAttributeMaxDynamicSharedMemorySize, SM1_TOTAL);
    cudaFuncSetAttribute(k_mma2, cudaFuncAttributeMaxDynamicSharedMemorySize, SM2_TOTAL);

    int pack_threads = 98304 + 16384 + 768;
    k_pack<<<(pack_threads + 255) / 256, 256>>>(W_ga, b_ga, W_la, b_la,
                                                W_gb, b_gb, W_lb, b_lb,
                                                W_go, b_go, W_lo);
    k_mma1<<<NRB1, NTHR, SM1_TOTAL>>>(values, ln_in_g, ln_in_b);
    k_redB1<<<dim3(6, 25), 256>>>();
    k_redB2<<<6, 256>>>();
    k_mma2<<<NRB1, NTHR, SM2_TOTAL>>>(ln_o_g, ln_o_b, b_lo, out);
}